// round 7
// baseline (speedup 1.0000x reference)
#include <cuda_runtime.h>
#include <cuda_bf16.h>
#include <cstdint>

// ---------------------------------------------------------------------------
// bs=2, seq=2048, embed=1024, heads=16, head_dim=64
// All GEMMs on bf16 mma.sync with 3-term hi/lo split. Softmax fp32.
// R7: 3-stage cp.async pipelines (1 sync/chunk) with XOR-swizzled smem
//     (16B-aligned cp.async dst + conflict-free ldmatrix), fused split.
// ---------------------------------------------------------------------------

#define SEQ   2048
#define EMB   1024
#define NH    16
#define HD    64
#define ROWS  4096

__device__ __nv_bfloat16  g_xh  [(size_t)ROWS * EMB];
__device__ __nv_bfloat16  g_xl  [(size_t)ROWS * EMB];
__device__ __nv_bfloat16  g_wqh [(size_t)3 * EMB * EMB];
__device__ __nv_bfloat16  g_wql [(size_t)3 * EMB * EMB];
__device__ __nv_bfloat16  g_woh [(size_t)EMB * EMB];
__device__ __nv_bfloat16  g_wol [(size_t)EMB * EMB];
__device__ __nv_bfloat16  g_qkvh[(size_t)ROWS * 3 * EMB];
__device__ __nv_bfloat16  g_qkvl[(size_t)ROWS * 3 * EMB];
__device__ __nv_bfloat16  g_ath [(size_t)ROWS * EMB];
__device__ __nv_bfloat16  g_atl [(size_t)ROWS * EMB];

// ---------------------------------------------------------------------------
__device__ __forceinline__ uint32_t smem_u32(const void* p) {
    uint32_t a;
    asm("{ .reg .u64 t; cvta.to.shared.u64 t, %1; cvt.u32.u64 %0, t; }"
        : "=r"(a) : "l"(p));
    return a;
}
__device__ __forceinline__ void cp_async16(uint32_t dst, const void* src) {
    asm volatile("cp.async.cg.shared.global [%0], [%1], 16;" :: "r"(dst), "l"(src));
}
__device__ __forceinline__ void cp_commit() { asm volatile("cp.async.commit_group;"); }
template<int N>
__device__ __forceinline__ void cp_wait() {
    asm volatile("cp.async.wait_group %0;" :: "n"(N));
}
__device__ __forceinline__ void ldsm_x4(uint32_t* r, uint32_t addr) {
    asm volatile("ldmatrix.sync.aligned.m8n8.x4.shared.b16 {%0,%1,%2,%3}, [%4];"
                 : "=r"(r[0]), "=r"(r[1]), "=r"(r[2]), "=r"(r[3]) : "r"(addr));
}
__device__ __forceinline__ void ldsm_x4t(uint32_t* r, uint32_t addr) {
    asm volatile("ldmatrix.sync.aligned.m8n8.x4.trans.shared.b16 {%0,%1,%2,%3}, [%4];"
                 : "=r"(r[0]), "=r"(r[1]), "=r"(r[2]), "=r"(r[3]) : "r"(addr));
}
__device__ __forceinline__ void mma16816(float* d, const uint32_t* a, const uint32_t* b) {
    asm volatile(
        "mma.sync.aligned.m16n8k16.row.col.f32.bf16.bf16.f32 "
        "{%0,%1,%2,%3}, {%4,%5,%6,%7}, {%8,%9}, {%0,%1,%2,%3};"
        : "+f"(d[0]), "+f"(d[1]), "+f"(d[2]), "+f"(d[3])
        : "r"(a[0]), "r"(a[1]), "r"(a[2]), "r"(a[3]), "r"(b[0]), "r"(b[1]));
}

// ---------------------------------------------------------------------------
// Fused fp32 -> bf16 (hi, lo) split for x, w_qkv, w_out in one launch.
// ---------------------------------------------------------------------------
#define XN   ((size_t)ROWS * EMB)
#define WQN  ((size_t)3 * EMB * EMB)
#define WON  ((size_t)EMB * EMB)
#define SPLIT_TOT (XN + WQN + WON)

__global__ __launch_bounds__(256)
void split_all(const float* __restrict__ x, const float* __restrict__ wq,
               const float* __restrict__ wo,
               __nv_bfloat16* __restrict__ xh, __nv_bfloat16* __restrict__ xl,
               __nv_bfloat16* __restrict__ wqh, __nv_bfloat16* __restrict__ wql,
               __nv_bfloat16* __restrict__ woh, __nv_bfloat16* __restrict__ wol)
{
    size_t i = ((size_t)blockIdx.x * 256 + threadIdx.x) * 4;
    const float* in; __nv_bfloat16 *hi, *lo; size_t off;
    if (i < XN)            { in = x;  hi = xh;  lo = xl;  off = i; }
    else if (i < XN + WQN) { in = wq; hi = wqh; lo = wql; off = i - XN; }
    else                   { in = wo; hi = woh; lo = wol; off = i - XN - WQN; }
    float4 v = *(const float4*)(in + off);
    __nv_bfloat162 h0 = __floats2bfloat162_rn(v.x, v.y);
    __nv_bfloat162 h1 = __floats2bfloat162_rn(v.z, v.w);
    __nv_bfloat162 l0 = __floats2bfloat162_rn(v.x - __low2float(h0), v.y - __high2float(h0));
    __nv_bfloat162 l1 = __floats2bfloat162_rn(v.z - __low2float(h1), v.w - __high2float(h1));
    *(__nv_bfloat162*)(hi + off)     = h0;
    *(__nv_bfloat162*)(hi + off + 2) = h1;
    *(__nv_bfloat162*)(lo + off)     = l0;
    *(__nv_bfloat162*)(lo + off + 2) = l1;
}

// ---------------------------------------------------------------------------
// bf16 split GEMM: C = A B^T (+bias), optional bf16 hi/lo output.
// 3-stage cp.async pipeline, 1 syncthreads per 32-K chunk.
// Smem layout per stage: 2 "pairs" (A, B). Each pair: 128 rows x 128B;
// a row holds hi chunks 0-3 (k0..k31) and lo chunks 4-7, stored at
// byte (chunk ^ (row&7))*16. 16B-aligned; ldmatrix conflict-free.
// ---------------------------------------------------------------------------
#define PAIR_B  16384                     // 128 rows * 128 B
#define STG_B   (2 * PAIR_B)              // 32768
#define GSMEM   (3 * STG_B)               // 98304

template<bool BIAS, bool SPLIT_OUT>
__global__ __launch_bounds__(256)
void gemm_mma(const __nv_bfloat16* __restrict__ Ah, const __nv_bfloat16* __restrict__ Al,
              const __nv_bfloat16* __restrict__ Bh, const __nv_bfloat16* __restrict__ Bl,
              const float* __restrict__ bias, float* __restrict__ C,
              __nv_bfloat16* __restrict__ Ch, __nv_bfloat16* __restrict__ Cl,
              int M, int N, int K)
{
    extern __shared__ char smem[];
    const uint32_t sbase = smem_u32(smem);

    const int t    = threadIdx.x;
    const int warp = t >> 5;
    const int lane = t & 31;
    const int wm   = warp >> 2;
    const int wn   = warp & 3;
    const int bm   = blockIdx.y * 128;
    const int bn   = blockIdx.x * 128;

    const int aRow = (lane & 15);
    const int aKh  = lane >> 4;
    const int bN   = ((lane >> 4) << 3) + (lane & 7);
    const int bKh  = (lane >> 3) & 1;

    float acc[4][4][4];
    #pragma unroll
    for (int i = 0; i < 4; i++)
        #pragma unroll
        for (int j = 0; j < 4; j++)
            #pragma unroll
            for (int r = 0; r < 4; r++) acc[i][j][r] = 0.f;

    const int nck = K >> 5;

    // loader: 8 x cp.async(16B) per thread per stage
    const int lchunk = t & 7;                       // 0..7
    const int lrbase = t >> 3;                      // 0..31
    auto load_chunk = [&](int ck, int stg) {
        const int k0 = ck << 5;
        const int ke = k0 + (lchunk & 3) * 8;
        #pragma unroll
        for (int it = 0; it < 8; it++) {
            const int pair = it >> 2;               // 0: A, 1: B
            const int row  = (it & 3) * 32 + lrbase;
            uint32_t dst = sbase + stg * STG_B + pair * PAIR_B
                         + row * 128 + ((lchunk ^ (row & 7)) << 4);
            const __nv_bfloat16* src;
            if (pair == 0) src = (lchunk < 4 ? Ah : Al) + (size_t)(bm + row) * K + ke;
            else           src = (lchunk < 4 ? Bh : Bl) + (size_t)(bn + row) * K + ke;
            cp_async16(dst, src);
        }
    };

    load_chunk(0, 0); cp_commit();
    load_chunk(1, 1); cp_commit();

    int stg = 0;
    for (int ck = 0; ck < nck; ck++) {
        if (ck + 1 < nck) cp_wait<1>(); else cp_wait<0>();
        __syncthreads();
        if (ck + 2 < nck) {
            int ns = stg + 2; if (ns >= 3) ns -= 3;
            load_chunk(ck + 2, ns); cp_commit();
        }

        const uint32_t stgb = sbase + stg * STG_B;
        #pragma unroll
        for (int ks = 0; ks < 2; ks++) {
            uint32_t ah[4][4], al[4][4], bh[4][2], bl[4][2];
            #pragma unroll
            for (int mi = 0; mi < 4; mi++) {
                const int row = wm * 64 + mi * 16 + aRow;
                const int ch  = ks * 2 + aKh;
                const uint32_t rb = stgb + row * 128;
                ldsm_x4(ah[mi], rb + ((ch       ^ (row & 7)) << 4));
                ldsm_x4(al[mi], rb + (((ch + 4) ^ (row & 7)) << 4));
            }
            #pragma unroll
            for (int p = 0; p < 2; p++) {
                const int row = wn * 32 + p * 16 + bN;
                const int ch  = ks * 2 + bKh;
                const uint32_t rb = stgb + PAIR_B + row * 128;
                uint32_t rh[4], rl[4];
                ldsm_x4(rh, rb + ((ch       ^ (row & 7)) << 4));
                ldsm_x4(rl, rb + (((ch + 4) ^ (row & 7)) << 4));
                bh[p * 2][0] = rh[0]; bh[p * 2][1] = rh[1];
                bh[p * 2 + 1][0] = rh[2]; bh[p * 2 + 1][1] = rh[3];
                bl[p * 2][0] = rl[0]; bl[p * 2][1] = rl[1];
                bl[p * 2 + 1][0] = rl[2]; bl[p * 2 + 1][1] = rl[3];
            }
            #pragma unroll
            for (int mi = 0; mi < 4; mi++)
                #pragma unroll
                for (int nj = 0; nj < 4; nj++) {
                    mma16816(acc[mi][nj], ah[mi], bh[nj]);
                    mma16816(acc[mi][nj], ah[mi], bl[nj]);
                    mma16816(acc[mi][nj], al[mi], bh[nj]);
                }
        }
        if (++stg == 3) stg = 0;
    }

    const int r0 = bm + wm * 64 + (lane >> 2);
    const int c0 = bn + wn * 32 + (lane & 3) * 2;
    #pragma unroll
    for (int mi = 0; mi < 4; mi++)
        #pragma unroll
        for (int nj = 0; nj < 4; nj++) {
            int row = r0 + mi * 16;
            int col = c0 + nj * 8;
            float2 v0 = make_float2(acc[mi][nj][0], acc[mi][nj][1]);
            float2 v1 = make_float2(acc[mi][nj][2], acc[mi][nj][3]);
            if (BIAS) {
                v0.x += bias[col]; v0.y += bias[col + 1];
                v1.x += bias[col]; v1.y += bias[col + 1];
            }
            if (SPLIT_OUT) {
                __nv_bfloat162 h0 = __floats2bfloat162_rn(v0.x, v0.y);
                __nv_bfloat162 h1 = __floats2bfloat162_rn(v1.x, v1.y);
                __nv_bfloat162 l0 = __floats2bfloat162_rn(v0.x - __low2float(h0),
                                                          v0.y - __high2float(h0));
                __nv_bfloat162 l1 = __floats2bfloat162_rn(v1.x - __low2float(h1),
                                                          v1.y - __high2float(h1));
                *(__nv_bfloat162*)(Ch + (size_t)row * N + col)       = h0;
                *(__nv_bfloat162*)(Ch + (size_t)(row + 8) * N + col) = h1;
                *(__nv_bfloat162*)(Cl + (size_t)row * N + col)       = l0;
                *(__nv_bfloat162*)(Cl + (size_t)(row + 8) * N + col) = l1;
            } else {
                *(float2*)(C + (size_t)row * N + col)       = v0;
                *(float2*)(C + (size_t)(row + 8) * N + col) = v1;
            }
        }
}

// ---------------------------------------------------------------------------
// Flash attention on mma.sync, 3-term split; 3-stage KV pipeline, 1 sync/blk.
// Padded stride 72 bf16 = 144 B (16B-aligned rows, conflict-free ldmatrix).
// ---------------------------------------------------------------------------
#define ATS    72
#define QTILE  (128 * ATS * 2)            // 18432
#define KVT    (64 * ATS * 2)             // 9216
#define KVSTG  (4 * KVT)                  // 36864
#define ASMEM  (3 * KVSTG)                // 110592

__global__ __launch_bounds__(256)
void attn_mma(const __nv_bfloat16* __restrict__ qh,
              const __nv_bfloat16* __restrict__ ql,
              __nv_bfloat16* __restrict__ oh,
              __nv_bfloat16* __restrict__ ol)
{
    extern __shared__ char smem[];
    const uint32_t sbase = smem_u32(smem);

    const int t    = threadIdx.x;
    const int warp = t >> 5;
    const int lane = t & 31;
    const int qb   = 15 - blockIdx.x;
    const int h    = blockIdx.y;
    const int b    = blockIdx.z;
    const int wr0  = warp * 16;

    const int aRow = lane & 15;
    const int aKh  = lane >> 4;
    const int bN   = ((lane >> 4) << 3) + (lane & 7);
    const int bKh  = (lane >> 3) & 1;
    const int vRow = ((lane >> 3) & 1) * 8 + (lane & 7);
    const int vCol = (lane >> 4) * 8;

    const size_t qrow0 = (size_t)b * SEQ + qb * 128;

    #pragma unroll
    for (int it = 0; it < 4; it++) {
        const int linear = it * 256 + t;
        const int row = linear >> 3;
        const int kc  = (linear & 7) << 3;
        uint32_t d = sbase + (row * ATS + kc) * 2;
        const size_t go = (qrow0 + row) * 3072 + h * 192 + kc;
        cp_async16(d,         qh + go);
        cp_async16(d + QTILE, ql + go);
    }
    cp_commit();
    cp_wait<0>();
    __syncthreads();

    uint32_t qfh[4][4], qfl[4][4];
    #pragma unroll
    for (int kt = 0; kt < 4; kt++) {
        uint32_t off = ((wr0 + aRow) * ATS + kt * 16 + aKh * 8) * 2;
        ldsm_x4(qfh[kt], sbase + off);
        ldsm_x4(qfl[kt], sbase + QTILE + off);
    }
    __syncthreads();

    float oacc[8][4];
    #pragma unroll
    for (int i = 0; i < 8; i++)
        #pragma unroll
        for (int j = 0; j < 4; j++) oacc[i][j] = 0.f;
    float m0 = -1e30f, m1 = -1e30f, l0 = 0.f, l1 = 0.f;

    const int r0g = qb * 128 + wr0 + (lane >> 2);
    const int r1g = r0g + 8;
    const int nblk = (qb + 1) * 2;

    auto load_kv = [&](int blk, int s) {
        const int j0 = blk * 64;
        const uint32_t kb = sbase + s * KVSTG;
        #pragma unroll
        for (int it = 0; it < 2; it++) {
            const int linear = it * 256 + t;
            const int row = linear >> 3;
            const int kc  = (linear & 7) << 3;
            uint32_t d = kb + (row * ATS + kc) * 2;
            const size_t gk = ((size_t)b * SEQ + j0 + row) * 3072 + h * 192 + 64 + kc;
            const size_t gv = gk + 64;
            cp_async16(d,           qh + gk);
            cp_async16(d + KVT,     ql + gk);
            cp_async16(d + 2 * KVT, qh + gv);
            cp_async16(d + 3 * KVT, ql + gv);
        }
    };

    load_kv(0, 0); cp_commit();
    if (nblk > 1) { load_kv(1, 1); cp_commit(); }

    int stg = 0;
    for (int blk = 0; blk < nblk; blk++) {
        const int j0 = blk * 64;
        if (blk + 1 < nblk) cp_wait<1>(); else cp_wait<0>();
        __syncthreads();
        if (blk + 2 < nblk) {
            int ns = stg + 2; if (ns >= 3) ns -= 3;
            load_kv(blk + 2, ns); cp_commit();
        }

        const bool active = (j0 <= qb * 128 + wr0 + 15);
        if (active) {
            const uint32_t kb = sbase + stg * KVSTG;

            float sacc[8][4];
            #pragma unroll
            for (int i = 0; i < 8; i++)
                #pragma unroll
                for (int j = 0; j < 4; j++) sacc[i][j] = 0.f;
            #pragma unroll
            for (int kt = 0; kt < 4; kt++) {
                #pragma unroll
                for (int nt2 = 0; nt2 < 4; nt2++) {
                    uint32_t off = ((nt2 * 16 + bN) * ATS + kt * 16 + bKh * 8) * 2;
                    uint32_t rh[4], rl[4];
                    ldsm_x4(rh, kb + off);
                    ldsm_x4(rl, kb + KVT + off);
                    uint32_t kh0[2] = {rh[0], rh[1]}, kh1[2] = {rh[2], rh[3]};
                    uint32_t kl0[2] = {rl[0], rl[1]}, kl1[2] = {rl[2], rl[3]};
                    mma16816(sacc[nt2 * 2],     qfh[kt], kh0);
                    mma16816(sacc[nt2 * 2],     qfh[kt], kl0);
                    mma16816(sacc[nt2 * 2],     qfl[kt], kh0);
                    mma16816(sacc[nt2 * 2 + 1], qfh[kt], kh1);
                    mma16816(sacc[nt2 * 2 + 1], qfh[kt], kl1);
                    mma16816(sacc[nt2 * 2 + 1], qfl[kt], kh1);
                }
            }

            if (j0 + 63 > qb * 128 + wr0) {
                #pragma unroll
                for (int nt = 0; nt < 8; nt++) {
                    const int c = j0 + nt * 8 + (lane & 3) * 2;
                    if (c     > r0g) sacc[nt][0] = -1e30f;
                    if (c + 1 > r0g) sacc[nt][1] = -1e30f;
                    if (c     > r1g) sacc[nt][2] = -1e30f;
                    if (c + 1 > r1g) sacc[nt][3] = -1e30f;
                }
            }

            float mx0 = -1e30f, mx1 = -1e30f;
            #pragma unroll
            for (int nt = 0; nt < 8; nt++) {
                mx0 = fmaxf(mx0, fmaxf(sacc[nt][0], sacc[nt][1]));
                mx1 = fmaxf(mx1, fmaxf(sacc[nt][2], sacc[nt][3]));
            }
            mx0 = fmaxf(mx0, __shfl_xor_sync(0xffffffffu, mx0, 1));
            mx0 = fmaxf(mx0, __shfl_xor_sync(0xffffffffu, mx0, 2));
            mx1 = fmaxf(mx1, __shfl_xor_sync(0xffffffffu, mx1, 1));
            mx1 = fmaxf(mx1, __shfl_xor_sync(0xffffffffu, mx1, 2));
            mx0 *= 0.125f; mx1 *= 0.125f;
            const float nm0 = fmaxf(m0, mx0), nm1 = fmaxf(m1, mx1);
            const float rs0 = __expf(m0 - nm0), rs1 = __expf(m1 - nm1);
            m0 = nm0; m1 = nm1;

            float sum0 = 0.f, sum1 = 0.f;
            #pragma unroll
            for (int nt = 0; nt < 8; nt++) {
                float p0 = __expf(fmaf(sacc[nt][0], 0.125f, -nm0));
                float p1 = __expf(fmaf(sacc[nt][1], 0.125f, -nm0));
                float p2 = __expf(fmaf(sacc[nt][2], 0.125f, -nm1));
                float p3 = __expf(fmaf(sacc[nt][3], 0.125f, -nm1));
                sacc[nt][0] = p0; sacc[nt][1] = p1;
                sacc[nt][2] = p2; sacc[nt][3] = p3;
                sum0 += p0 + p1; sum1 += p2 + p3;
            }
            sum0 += __shfl_xor_sync(0xffffffffu, sum0, 1);
            sum0 += __shfl_xor_sync(0xffffffffu, sum0, 2);
            sum1 += __shfl_xor_sync(0xffffffffu, sum1, 1);
            sum1 += __shfl_xor_sync(0xffffffffu, sum1, 2);
            l0 = l0 * rs0 + sum0;
            l1 = l1 * rs1 + sum1;

            #pragma unroll
            for (int dt = 0; dt < 8; dt++) {
                oacc[dt][0] *= rs0; oacc[dt][1] *= rs0;
                oacc[dt][2] *= rs1; oacc[dt][3] *= rs1;
            }

            #pragma unroll
            for (int kt = 0; kt < 4; kt++) {
                uint32_t vh[8][2], vl[8][2];
                #pragma unroll
                for (int dt2 = 0; dt2 < 4; dt2++) {
                    uint32_t off = ((kt * 16 + vRow) * ATS + dt2 * 16 + vCol) * 2;
                    uint32_t rh[4], rl[4];
                    ldsm_x4t(rh, kb + 2 * KVT + off);
                    ldsm_x4t(rl, kb + 3 * KVT + off);
                    vh[dt2 * 2][0] = rh[0]; vh[dt2 * 2][1] = rh[1];
                    vh[dt2 * 2 + 1][0] = rh[2]; vh[dt2 * 2 + 1][1] = rh[3];
                    vl[dt2 * 2][0] = rl[0]; vl[dt2 * 2][1] = rl[1];
                    vl[dt2 * 2 + 1][0] = rl[2]; vl[dt2 * 2 + 1][1] = rl[3];
                }
                uint32_t Ah4[4], Al4[4];
                #pragma unroll
                for (int half = 0; half < 2; half++) {
                    const float* s = sacc[kt * 2 + half];
                    __nv_bfloat162 h01 = __floats2bfloat162_rn(s[0], s[1]);
                    __nv_bfloat162 h23 = __floats2bfloat162_rn(s[2], s[3]);
                    Ah4[half * 2]     = *(uint32_t*)&h01;
                    Ah4[half * 2 + 1] = *(uint32_t*)&h23;
                    __nv_bfloat162 l01 = __floats2bfloat162_rn(
                        s[0] - __low2float(h01), s[1] - __high2float(h01));
                    __nv_bfloat162 l23 = __floats2bfloat162_rn(
                        s[2] - __low2float(h23), s[3] - __high2float(h23));
                    Al4[half * 2]     = *(uint32_t*)&l01;
                    Al4[half * 2 + 1] = *(uint32_t*)&l23;
                }
                #pragma unroll
                for (int dt = 0; dt < 8; dt++) {
                    mma16816(oacc[dt], Ah4, vh[dt]);
                    mma16816(oacc[dt], Ah4, vl[dt]);
                    mma16816(oacc[dt], Al4, vh[dt]);
                }
            }
        }
        if (++stg == 3) stg = 0;
    }

    const float inv0 = 1.f / l0, inv1 = 1.f / l1;
    const size_t ro0 = (size_t)b * SEQ + qb * 128 + wr0 + (lane >> 2);
    const size_t ro1 = ro0 + 8;
    #pragma unroll
    for (int dt = 0; dt < 8; dt++) {
        const int col = h * 64 + dt * 8 + (lane & 3) * 2;
        float x0 = oacc[dt][0] * inv0, y0 = oacc[dt][1] * inv0;
        float x1 = oacc[dt][2] * inv1, y1 = oacc[dt][3] * inv1;
        __nv_bfloat162 h0 = __floats2bfloat162_rn(x0, y0);
        __nv_bfloat162 h1 = __floats2bfloat162_rn(x1, y1);
        __nv_bfloat162 e0 = __floats2bfloat162_rn(x0 - __low2float(h0), y0 - __high2float(h0));
        __nv_bfloat162 e1 = __floats2bfloat162_rn(x1 - __low2float(h1), y1 - __high2float(h1));
        *(__nv_bfloat162*)(oh + ro0 * EMB + col) = h0;
        *(__nv_bfloat162*)(oh + ro1 * EMB + col) = h1;
        *(__nv_bfloat162*)(ol + ro0 * EMB + col) = e0;
        *(__nv_bfloat162*)(ol + ro1 * EMB + col) = e1;
    }
}

// ---------------------------------------------------------------------------
extern "C" void kernel_launch(void* const* d_in, const int* in_sizes, int n_in,
                              void* d_out, int out_size)
{
    const float* x    = (const float*)d_in[0];
    const float* wqkv = (const float*)d_in[1];
    const float* wout = (const float*)d_in[2];
    const float* bout = (const float*)d_in[3];
    float* out = (float*)d_out;

    __nv_bfloat16 *xh, *xl, *wqh, *wql, *woh, *wol, *qkvh, *qkvl, *ath, *atl;
    cudaGetSymbolAddress((void**)&xh,   g_xh);
    cudaGetSymbolAddress((void**)&xl,   g_xl);
    cudaGetSymbolAddress((void**)&wqh,  g_wqh);
    cudaGetSymbolAddress((void**)&wql,  g_wql);
    cudaGetSymbolAddress((void**)&woh,  g_woh);
    cudaGetSymbolAddress((void**)&wol,  g_wol);
    cudaGetSymbolAddress((void**)&qkvh, g_qkvh);
    cudaGetSymbolAddress((void**)&qkvl, g_qkvl);
    cudaGetSymbolAddress((void**)&ath,  g_ath);
    cudaGetSymbolAddress((void**)&atl,  g_atl);

    cudaFuncSetAttribute(gemm_mma<false, true>,
                         cudaFuncAttributeMaxDynamicSharedMemorySize, GSMEM);
    cudaFuncSetAttribute(gemm_mma<true, false>,
                         cudaFuncAttributeMaxDynamicSharedMemorySize, GSMEM);
    cudaFuncSetAttribute(attn_mma,
                         cudaFuncAttributeMaxDynamicSharedMemorySize, ASMEM);

    split_all<<<SPLIT_TOT / 1024, 256>>>(x, wqkv, wout,
                                         xh, xl, wqh, wql, woh, wol);

    gemm_mma<false, true><<<dim3(3072 / 128, ROWS / 128), 256, GSMEM>>>(
        xh, xl, wqh, wql, nullptr, nullptr, qkvh, qkvl, ROWS, 3072, EMB);

    attn_mma<<<dim3(SEQ / 128, NH, 2), 256, ASMEM>>>(qkvh, qkvl, ath, atl);

    gemm_mma<true, false><<<dim3(EMB / 128, ROWS / 128), 256, GSMEM>>>(
        ath, atl, woh, wol, bout, out, nullptr, nullptr, ROWS, EMB, EMB);
}

// round 8
// speedup vs baseline: 1.0929x; 1.0929x over previous
#include <cuda_runtime.h>
#include <cuda_bf16.h>
#include <cstdint>

// ---------------------------------------------------------------------------
// bs=2, seq=2048, embed=1024, heads=16, head_dim=64
// All GEMMs on bf16 mma.sync with 3-term hi/lo split. Softmax fp32.
// R8: GEMM reworked to 4 warps x 64x64 warp tiles (128 thr/CTA) to halve
//     smem crossbar read traffic (was the measured bottleneck, not barriers).
// ---------------------------------------------------------------------------

#define SEQ   2048
#define EMB   1024
#define NH    16
#define HD    64
#define ROWS  4096

__device__ __nv_bfloat16  g_xh  [(size_t)ROWS * EMB];
__device__ __nv_bfloat16  g_xl  [(size_t)ROWS * EMB];
__device__ __nv_bfloat16  g_wqh [(size_t)3 * EMB * EMB];
__device__ __nv_bfloat16  g_wql [(size_t)3 * EMB * EMB];
__device__ __nv_bfloat16  g_woh [(size_t)EMB * EMB];
__device__ __nv_bfloat16  g_wol [(size_t)EMB * EMB];
__device__ __nv_bfloat16  g_qkvh[(size_t)ROWS * 3 * EMB];
__device__ __nv_bfloat16  g_qkvl[(size_t)ROWS * 3 * EMB];
__device__ __nv_bfloat16  g_ath [(size_t)ROWS * EMB];
__device__ __nv_bfloat16  g_atl [(size_t)ROWS * EMB];

// ---------------------------------------------------------------------------
__device__ __forceinline__ uint32_t smem_u32(const void* p) {
    uint32_t a;
    asm("{ .reg .u64 t; cvta.to.shared.u64 t, %1; cvt.u32.u64 %0, t; }"
        : "=r"(a) : "l"(p));
    return a;
}
__device__ __forceinline__ void cp_async16(uint32_t dst, const void* src) {
    asm volatile("cp.async.cg.shared.global [%0], [%1], 16;" :: "r"(dst), "l"(src));
}
__device__ __forceinline__ void cp_commit() { asm volatile("cp.async.commit_group;"); }
template<int N>
__device__ __forceinline__ void cp_wait() {
    asm volatile("cp.async.wait_group %0;" :: "n"(N));
}
__device__ __forceinline__ void ldsm_x4(uint32_t* r, uint32_t addr) {
    asm volatile("ldmatrix.sync.aligned.m8n8.x4.shared.b16 {%0,%1,%2,%3}, [%4];"
                 : "=r"(r[0]), "=r"(r[1]), "=r"(r[2]), "=r"(r[3]) : "r"(addr));
}
__device__ __forceinline__ void ldsm_x4t(uint32_t* r, uint32_t addr) {
    asm volatile("ldmatrix.sync.aligned.m8n8.x4.trans.shared.b16 {%0,%1,%2,%3}, [%4];"
                 : "=r"(r[0]), "=r"(r[1]), "=r"(r[2]), "=r"(r[3]) : "r"(addr));
}
__device__ __forceinline__ void mma16816(float* d, const uint32_t* a, const uint32_t* b) {
    asm volatile(
        "mma.sync.aligned.m16n8k16.row.col.f32.bf16.bf16.f32 "
        "{%0,%1,%2,%3}, {%4,%5,%6,%7}, {%8,%9}, {%0,%1,%2,%3};"
        : "+f"(d[0]), "+f"(d[1]), "+f"(d[2]), "+f"(d[3])
        : "r"(a[0]), "r"(a[1]), "r"(a[2]), "r"(a[3]), "r"(b[0]), "r"(b[1]));
}

// ---------------------------------------------------------------------------
// Fused fp32 -> bf16 (hi, lo) split for x, w_qkv, w_out in one launch.
// ---------------------------------------------------------------------------
#define XN   ((size_t)ROWS * EMB)
#define WQN  ((size_t)3 * EMB * EMB)
#define WON  ((size_t)EMB * EMB)
#define SPLIT_TOT (XN + WQN + WON)

__global__ __launch_bounds__(256)
void split_all(const float* __restrict__ x, const float* __restrict__ wq,
               const float* __restrict__ wo,
               __nv_bfloat16* __restrict__ xh, __nv_bfloat16* __restrict__ xl,
               __nv_bfloat16* __restrict__ wqh, __nv_bfloat16* __restrict__ wql,
               __nv_bfloat16* __restrict__ woh, __nv_bfloat16* __restrict__ wol)
{
    size_t i = ((size_t)blockIdx.x * 256 + threadIdx.x) * 4;
    const float* in; __nv_bfloat16 *hi, *lo; size_t off;
    if (i < XN)            { in = x;  hi = xh;  lo = xl;  off = i; }
    else if (i < XN + WQN) { in = wq; hi = wqh; lo = wql; off = i - XN; }
    else                   { in = wo; hi = woh; lo = wol; off = i - XN - WQN; }
    float4 v = *(const float4*)(in + off);
    __nv_bfloat162 h0 = __floats2bfloat162_rn(v.x, v.y);
    __nv_bfloat162 h1 = __floats2bfloat162_rn(v.z, v.w);
    __nv_bfloat162 l0 = __floats2bfloat162_rn(v.x - __low2float(h0), v.y - __high2float(h0));
    __nv_bfloat162 l1 = __floats2bfloat162_rn(v.z - __low2float(h1), v.w - __high2float(h1));
    *(__nv_bfloat162*)(hi + off)     = h0;
    *(__nv_bfloat162*)(hi + off + 2) = h1;
    *(__nv_bfloat162*)(lo + off)     = l0;
    *(__nv_bfloat162*)(lo + off + 2) = l1;
}

// ---------------------------------------------------------------------------
// bf16 split GEMM: C = A B^T (+bias), optional bf16 hi/lo output.
// CTA 128x128, 128 threads = 4 warps of 64x64 warp tiles.
// 3-stage cp.async pipeline; XOR-swizzled smem rows (128B: hi chunks 0-3,
// lo chunks 4-7 at byte (chunk ^ (row&7))*16). 16B-aligned, conflict-free.
// ---------------------------------------------------------------------------
#define PAIR_B  16384                     // 128 rows * 128 B
#define STG_B   (2 * PAIR_B)              // 32768
#define GSMEM   (3 * STG_B)               // 98304

template<bool BIAS, bool SPLIT_OUT>
__global__ __launch_bounds__(128)
void gemm_mma(const __nv_bfloat16* __restrict__ Ah, const __nv_bfloat16* __restrict__ Al,
              const __nv_bfloat16* __restrict__ Bh, const __nv_bfloat16* __restrict__ Bl,
              const float* __restrict__ bias, float* __restrict__ C,
              __nv_bfloat16* __restrict__ Ch, __nv_bfloat16* __restrict__ Cl,
              int M, int N, int K)
{
    extern __shared__ char smem[];
    const uint32_t sbase = smem_u32(smem);

    const int t    = threadIdx.x;
    const int warp = t >> 5;
    const int lane = t & 31;
    const int wm   = warp >> 1;           // 0..1 -> m offset *64
    const int wn   = warp & 1;            // 0..1 -> n offset *64
    const int bm   = blockIdx.y * 128;
    const int bn   = blockIdx.x * 128;

    const int aRow = (lane & 15);
    const int aKh  = lane >> 4;
    const int bN   = ((lane >> 4) << 3) + (lane & 7);
    const int bKh  = (lane >> 3) & 1;

    float acc[4][8][4];
    #pragma unroll
    for (int i = 0; i < 4; i++)
        #pragma unroll
        for (int j = 0; j < 8; j++)
            #pragma unroll
            for (int r = 0; r < 4; r++) acc[i][j][r] = 0.f;

    const int nck = K >> 5;

    // loader: 16 x cp.async(16B) per thread per stage (128 thr * 16 * 16B = 32KB)
    const int lchunk = t & 7;             // 0..7 (hi: 0-3, lo: 4-7)
    const int lrow   = t >> 3;            // 0..15
    auto load_chunk = [&](int ck, int stg) {
        const int ke = (ck << 5) + (lchunk & 3) * 8;
        #pragma unroll
        for (int it = 0; it < 16; it++) {
            const int pair = it >> 3;                 // 0: A, 1: B
            const int row  = (it & 7) * 16 + lrow;    // 0..127
            uint32_t dst = sbase + stg * STG_B + pair * PAIR_B
                         + row * 128 + ((lchunk ^ (row & 7)) << 4);
            const __nv_bfloat16* src;
            if (pair == 0) src = (lchunk < 4 ? Ah : Al) + (size_t)(bm + row) * K + ke;
            else           src = (lchunk < 4 ? Bh : Bl) + (size_t)(bn + row) * K + ke;
            cp_async16(dst, src);
        }
    };

    load_chunk(0, 0); cp_commit();
    load_chunk(1, 1); cp_commit();

    int stg = 0;
    for (int ck = 0; ck < nck; ck++) {
        if (ck + 1 < nck) cp_wait<1>(); else cp_wait<0>();
        __syncthreads();
        if (ck + 2 < nck) {
            int ns = stg + 2; if (ns >= 3) ns -= 3;
            load_chunk(ck + 2, ns); cp_commit();
        }

        const uint32_t stgb = sbase + stg * STG_B;
        #pragma unroll
        for (int ks = 0; ks < 2; ks++) {
            uint32_t ah[4][4], al[4][4], bh[8][2], bl[8][2];
            #pragma unroll
            for (int mi = 0; mi < 4; mi++) {
                const int row = wm * 64 + mi * 16 + aRow;
                const int ch  = ks * 2 + aKh;
                const uint32_t rb = stgb + row * 128;
                ldsm_x4(ah[mi], rb + ((ch       ^ (row & 7)) << 4));
                ldsm_x4(al[mi], rb + (((ch + 4) ^ (row & 7)) << 4));
            }
            #pragma unroll
            for (int p = 0; p < 4; p++) {
                const int row = wn * 64 + p * 16 + bN;
                const int ch  = ks * 2 + bKh;
                const uint32_t rb = stgb + PAIR_B + row * 128;
                uint32_t rh[4], rl[4];
                ldsm_x4(rh, rb + ((ch       ^ (row & 7)) << 4));
                ldsm_x4(rl, rb + (((ch + 4) ^ (row & 7)) << 4));
                bh[p * 2][0] = rh[0]; bh[p * 2][1] = rh[1];
                bh[p * 2 + 1][0] = rh[2]; bh[p * 2 + 1][1] = rh[3];
                bl[p * 2][0] = rl[0]; bl[p * 2][1] = rl[1];
                bl[p * 2 + 1][0] = rl[2]; bl[p * 2 + 1][1] = rl[3];
            }
            #pragma unroll
            for (int mi = 0; mi < 4; mi++)
                #pragma unroll
                for (int nj = 0; nj < 8; nj++) {
                    mma16816(acc[mi][nj], ah[mi], bh[nj]);
                    mma16816(acc[mi][nj], ah[mi], bl[nj]);
                    mma16816(acc[mi][nj], al[mi], bh[nj]);
                }
        }
        if (++stg == 3) stg = 0;
    }

    const int r0 = bm + wm * 64 + (lane >> 2);
    const int c0 = bn + wn * 64 + (lane & 3) * 2;
    #pragma unroll
    for (int mi = 0; mi < 4; mi++)
        #pragma unroll
        for (int nj = 0; nj < 8; nj++) {
            int row = r0 + mi * 16;
            int col = c0 + nj * 8;
            float2 v0 = make_float2(acc[mi][nj][0], acc[mi][nj][1]);
            float2 v1 = make_float2(acc[mi][nj][2], acc[mi][nj][3]);
            if (BIAS) {
                v0.x += bias[col]; v0.y += bias[col + 1];
                v1.x += bias[col]; v1.y += bias[col + 1];
            }
            if (SPLIT_OUT) {
                __nv_bfloat162 h0 = __floats2bfloat162_rn(v0.x, v0.y);
                __nv_bfloat162 h1 = __floats2bfloat162_rn(v1.x, v1.y);
                __nv_bfloat162 l0 = __floats2bfloat162_rn(v0.x - __low2float(h0),
                                                          v0.y - __high2float(h0));
                __nv_bfloat162 l1 = __floats2bfloat162_rn(v1.x - __low2float(h1),
                                                          v1.y - __high2float(h1));
                *(__nv_bfloat162*)(Ch + (size_t)row * N + col)       = h0;
                *(__nv_bfloat162*)(Ch + (size_t)(row + 8) * N + col) = h1;
                *(__nv_bfloat162*)(Cl + (size_t)row * N + col)       = l0;
                *(__nv_bfloat162*)(Cl + (size_t)(row + 8) * N + col) = l1;
            } else {
                *(float2*)(C + (size_t)row * N + col)       = v0;
                *(float2*)(C + (size_t)(row + 8) * N + col) = v1;
            }
        }
}

// ---------------------------------------------------------------------------
// Flash attention on mma.sync, 3-term split; 3-stage KV pipeline, 1 sync/blk.
// (unchanged from R7 — passes; ~195us)
// ---------------------------------------------------------------------------
#define ATS    72
#define QTILE  (128 * ATS * 2)
#define KVT    (64 * ATS * 2)
#define KVSTG  (4 * KVT)
#define ASMEM  (3 * KVSTG)

__global__ __launch_bounds__(256)
void attn_mma(const __nv_bfloat16* __restrict__ qh,
              const __nv_bfloat16* __restrict__ ql,
              __nv_bfloat16* __restrict__ oh,
              __nv_bfloat16* __restrict__ ol)
{
    extern __shared__ char smem[];
    const uint32_t sbase = smem_u32(smem);

    const int t    = threadIdx.x;
    const int warp = t >> 5;
    const int lane = t & 31;
    const int qb   = 15 - blockIdx.x;
    const int h    = blockIdx.y;
    const int b    = blockIdx.z;
    const int wr0  = warp * 16;

    const int aRow = lane & 15;
    const int aKh  = lane >> 4;
    const int bN   = ((lane >> 4) << 3) + (lane & 7);
    const int bKh  = (lane >> 3) & 1;
    const int vRow = ((lane >> 3) & 1) * 8 + (lane & 7);
    const int vCol = (lane >> 4) * 8;

    const size_t qrow0 = (size_t)b * SEQ + qb * 128;

    #pragma unroll
    for (int it = 0; it < 4; it++) {
        const int linear = it * 256 + t;
        const int row = linear >> 3;
        const int kc  = (linear & 7) << 3;
        uint32_t d = sbase + (row * ATS + kc) * 2;
        const size_t go = (qrow0 + row) * 3072 + h * 192 + kc;
        cp_async16(d,         qh + go);
        cp_async16(d + QTILE, ql + go);
    }
    cp_commit();
    cp_wait<0>();
    __syncthreads();

    uint32_t qfh[4][4], qfl[4][4];
    #pragma unroll
    for (int kt = 0; kt < 4; kt++) {
        uint32_t off = ((wr0 + aRow) * ATS + kt * 16 + aKh * 8) * 2;
        ldsm_x4(qfh[kt], sbase + off);
        ldsm_x4(qfl[kt], sbase + QTILE + off);
    }
    __syncthreads();

    float oacc[8][4];
    #pragma unroll
    for (int i = 0; i < 8; i++)
        #pragma unroll
        for (int j = 0; j < 4; j++) oacc[i][j] = 0.f;
    float m0 = -1e30f, m1 = -1e30f, l0 = 0.f, l1 = 0.f;

    const int r0g = qb * 128 + wr0 + (lane >> 2);
    const int r1g = r0g + 8;
    const int nblk = (qb + 1) * 2;

    auto load_kv = [&](int blk, int s) {
        const int j0 = blk * 64;
        const uint32_t kb = sbase + s * KVSTG;
        #pragma unroll
        for (int it = 0; it < 2; it++) {
            const int linear = it * 256 + t;
            const int row = linear >> 3;
            const int kc  = (linear & 7) << 3;
            uint32_t d = kb + (row * ATS + kc) * 2;
            const size_t gk = ((size_t)b * SEQ + j0 + row) * 3072 + h * 192 + 64 + kc;
            const size_t gv = gk + 64;
            cp_async16(d,           qh + gk);
            cp_async16(d + KVT,     ql + gk);
            cp_async16(d + 2 * KVT, qh + gv);
            cp_async16(d + 3 * KVT, ql + gv);
        }
    };

    load_kv(0, 0); cp_commit();
    if (nblk > 1) { load_kv(1, 1); cp_commit(); }

    int stg = 0;
    for (int blk = 0; blk < nblk; blk++) {
        const int j0 = blk * 64;
        if (blk + 1 < nblk) cp_wait<1>(); else cp_wait<0>();
        __syncthreads();
        if (blk + 2 < nblk) {
            int ns = stg + 2; if (ns >= 3) ns -= 3;
            load_kv(blk + 2, ns); cp_commit();
        }

        const bool active = (j0 <= qb * 128 + wr0 + 15);
        if (active) {
            const uint32_t kb = sbase + stg * KVSTG;

            float sacc[8][4];
            #pragma unroll
            for (int i = 0; i < 8; i++)
                #pragma unroll
                for (int j = 0; j < 4; j++) sacc[i][j] = 0.f;
            #pragma unroll
            for (int kt = 0; kt < 4; kt++) {
                #pragma unroll
                for (int nt2 = 0; nt2 < 4; nt2++) {
                    uint32_t off = ((nt2 * 16 + bN) * ATS + kt * 16 + bKh * 8) * 2;
                    uint32_t rh[4], rl[4];
                    ldsm_x4(rh, kb + off);
                    ldsm_x4(rl, kb + KVT + off);
                    uint32_t kh0[2] = {rh[0], rh[1]}, kh1[2] = {rh[2], rh[3]};
                    uint32_t kl0[2] = {rl[0], rl[1]}, kl1[2] = {rl[2], rl[3]};
                    mma16816(sacc[nt2 * 2],     qfh[kt], kh0);
                    mma16816(sacc[nt2 * 2],     qfh[kt], kl0);
                    mma16816(sacc[nt2 * 2],     qfl[kt], kh0);
                    mma16816(sacc[nt2 * 2 + 1], qfh[kt], kh1);
                    mma16816(sacc[nt2 * 2 + 1], qfh[kt], kl1);
                    mma16816(sacc[nt2 * 2 + 1], qfl[kt], kh1);
                }
            }

            if (j0 + 63 > qb * 128 + wr0) {
                #pragma unroll
                for (int nt = 0; nt < 8; nt++) {
                    const int c = j0 + nt * 8 + (lane & 3) * 2;
                    if (c     > r0g) sacc[nt][0] = -1e30f;
                    if (c + 1 > r0g) sacc[nt][1] = -1e30f;
                    if (c     > r1g) sacc[nt][2] = -1e30f;
                    if (c + 1 > r1g) sacc[nt][3] = -1e30f;
                }
            }

            float mx0 = -1e30f, mx1 = -1e30f;
            #pragma unroll
            for (int nt = 0; nt < 8; nt++) {
                mx0 = fmaxf(mx0, fmaxf(sacc[nt][0], sacc[nt][1]));
                mx1 = fmaxf(mx1, fmaxf(sacc[nt][2], sacc[nt][3]));
            }
            mx0 = fmaxf(mx0, __shfl_xor_sync(0xffffffffu, mx0, 1));
            mx0 = fmaxf(mx0, __shfl_xor_sync(0xffffffffu, mx0, 2));
            mx1 = fmaxf(mx1, __shfl_xor_sync(0xffffffffu, mx1, 1));
            mx1 = fmaxf(mx1, __shfl_xor_sync(0xffffffffu, mx1, 2));
            mx0 *= 0.125f; mx1 *= 0.125f;
            const float nm0 = fmaxf(m0, mx0), nm1 = fmaxf(m1, mx1);
            const float rs0 = __expf(m0 - nm0), rs1 = __expf(m1 - nm1);
            m0 = nm0; m1 = nm1;

            float sum0 = 0.f, sum1 = 0.f;
            #pragma unroll
            for (int nt = 0; nt < 8; nt++) {
                float p0 = __expf(fmaf(sacc[nt][0], 0.125f, -nm0));
                float p1 = __expf(fmaf(sacc[nt][1], 0.125f, -nm0));
                float p2 = __expf(fmaf(sacc[nt][2], 0.125f, -nm1));
                float p3 = __expf(fmaf(sacc[nt][3], 0.125f, -nm1));
                sacc[nt][0] = p0; sacc[nt][1] = p1;
                sacc[nt][2] = p2; sacc[nt][3] = p3;
                sum0 += p0 + p1; sum1 += p2 + p3;
            }
            sum0 += __shfl_xor_sync(0xffffffffu, sum0, 1);
            sum0 += __shfl_xor_sync(0xffffffffu, sum0, 2);
            sum1 += __shfl_xor_sync(0xffffffffu, sum1, 1);
            sum1 += __shfl_xor_sync(0xffffffffu, sum1, 2);
            l0 = l0 * rs0 + sum0;
            l1 = l1 * rs1 + sum1;

            #pragma unroll
            for (int dt = 0; dt < 8; dt++) {
                oacc[dt][0] *= rs0; oacc[dt][1] *= rs0;
                oacc[dt][2] *= rs1; oacc[dt][3] *= rs1;
            }

            #pragma unroll
            for (int kt = 0; kt < 4; kt++) {
                uint32_t vh[8][2], vl[8][2];
                #pragma unroll
                for (int dt2 = 0; dt2 < 4; dt2++) {
                    uint32_t off = ((kt * 16 + vRow) * ATS + dt2 * 16 + vCol) * 2;
                    uint32_t rh[4], rl[4];
                    ldsm_x4t(rh, kb + 2 * KVT + off);
                    ldsm_x4t(rl, kb + 3 * KVT + off);
                    vh[dt2 * 2][0] = rh[0]; vh[dt2 * 2][1] = rh[1];
                    vh[dt2 * 2 + 1][0] = rh[2]; vh[dt2 * 2 + 1][1] = rh[3];
                    vl[dt2 * 2][0] = rl[0]; vl[dt2 * 2][1] = rl[1];
                    vl[dt2 * 2 + 1][0] = rl[2]; vl[dt2 * 2 + 1][1] = rl[3];
                }
                uint32_t Ah4[4], Al4[4];
                #pragma unroll
                for (int half = 0; half < 2; half++) {
                    const float* s = sacc[kt * 2 + half];
                    __nv_bfloat162 h01 = __floats2bfloat162_rn(s[0], s[1]);
                    __nv_bfloat162 h23 = __floats2bfloat162_rn(s[2], s[3]);
                    Ah4[half * 2]     = *(uint32_t*)&h01;
                    Ah4[half * 2 + 1] = *(uint32_t*)&h23;
                    __nv_bfloat162 l01 = __floats2bfloat162_rn(
                        s[0] - __low2float(h01), s[1] - __high2float(h01));
                    __nv_bfloat162 l23 = __floats2bfloat162_rn(
                        s[2] - __low2float(h23), s[3] - __high2float(h23));
                    Al4[half * 2]     = *(uint32_t*)&l01;
                    Al4[half * 2 + 1] = *(uint32_t*)&l23;
                }
                #pragma unroll
                for (int dt = 0; dt < 8; dt++) {
                    mma16816(oacc[dt], Ah4, vh[dt]);
                    mma16816(oacc[dt], Ah4, vl[dt]);
                    mma16816(oacc[dt], Al4, vh[dt]);
                }
            }
        }
        if (++stg == 3) stg = 0;
    }

    const float inv0 = 1.f / l0, inv1 = 1.f / l1;
    const size_t ro0 = (size_t)b * SEQ + qb * 128 + wr0 + (lane >> 2);
    const size_t ro1 = ro0 + 8;
    #pragma unroll
    for (int dt = 0; dt < 8; dt++) {
        const int col = h * 64 + dt * 8 + (lane & 3) * 2;
        float x0 = oacc[dt][0] * inv0, y0 = oacc[dt][1] * inv0;
        float x1 = oacc[dt][2] * inv1, y1 = oacc[dt][3] * inv1;
        __nv_bfloat162 h0 = __floats2bfloat162_rn(x0, y0);
        __nv_bfloat162 h1 = __floats2bfloat162_rn(x1, y1);
        __nv_bfloat162 e0 = __floats2bfloat162_rn(x0 - __low2float(h0), y0 - __high2float(h0));
        __nv_bfloat162 e1 = __floats2bfloat162_rn(x1 - __low2float(h1), y1 - __high2float(h1));
        *(__nv_bfloat162*)(oh + ro0 * EMB + col) = h0;
        *(__nv_bfloat162*)(oh + ro1 * EMB + col) = h1;
        *(__nv_bfloat162*)(ol + ro0 * EMB + col) = e0;
        *(__nv_bfloat162*)(ol + ro1 * EMB + col) = e1;
    }
}

// ---------------------------------------------------------------------------
extern "C" void kernel_launch(void* const* d_in, const int* in_sizes, int n_in,
                              void* d_out, int out_size)
{
    const float* x    = (const float*)d_in[0];
    const float* wqkv = (const float*)d_in[1];
    const float* wout = (const float*)d_in[2];
    const float* bout = (const float*)d_in[3];
    float* out = (float*)d_out;

    __nv_bfloat16 *xh, *xl, *wqh, *wql, *woh, *wol, *qkvh, *qkvl, *ath, *atl;
    cudaGetSymbolAddress((void**)&xh,   g_xh);
    cudaGetSymbolAddress((void**)&xl,   g_xl);
    cudaGetSymbolAddress((void**)&wqh,  g_wqh);
    cudaGetSymbolAddress((void**)&wql,  g_wql);
    cudaGetSymbolAddress((void**)&woh,  g_woh);
    cudaGetSymbolAddress((void**)&wol,  g_wol);
    cudaGetSymbolAddress((void**)&qkvh, g_qkvh);
    cudaGetSymbolAddress((void**)&qkvl, g_qkvl);
    cudaGetSymbolAddress((void**)&ath,  g_ath);
    cudaGetSymbolAddress((void**)&atl,  g_atl);

    cudaFuncSetAttribute(gemm_mma<false, true>,
                         cudaFuncAttributeMaxDynamicSharedMemorySize, GSMEM);
    cudaFuncSetAttribute(gemm_mma<true, false>,
                         cudaFuncAttributeMaxDynamicSharedMemorySize, GSMEM);
    cudaFuncSetAttribute(attn_mma,
                         cudaFuncAttributeMaxDynamicSharedMemorySize, ASMEM);

    split_all<<<SPLIT_TOT / 1024, 256>>>(x, wqkv, wout,
                                         xh, xl, wqh, wql, woh, wol);

    gemm_mma<false, true><<<dim3(3072 / 128, ROWS / 128), 128, GSMEM>>>(
        xh, xl, wqh, wql, nullptr, nullptr, qkvh, qkvl, ROWS, 3072, EMB);

    attn_mma<<<dim3(SEQ / 128, NH, 2), 256, ASMEM>>>(qkvh, qkvl, ath, atl);

    gemm_mma<true, false><<<dim3(EMB / 128, ROWS / 128), 128, GSMEM>>>(
        ath, atl, woh, wol, bout, out, nullptr, nullptr, ROWS, EMB, EMB);
}

// round 9
// speedup vs baseline: 1.4435x; 1.3208x over previous
#include <cuda_runtime.h>
#include <cuda_bf16.h>
#include <cuda_fp16.h>
#include <cstdint>

// ---------------------------------------------------------------------------
// bs=2, seq=2048, embed=1024, heads=16, head_dim=64
// R9: projections = 3-term bf16 split mma (fp32-accurate);
//     attention interior = single-term fp16 mma (err ~2^-12, within budget).
// ---------------------------------------------------------------------------

#define SEQ   2048
#define EMB   1024
#define NH    16
#define HD    64
#define ROWS  4096

__device__ __nv_bfloat16  g_xh  [(size_t)ROWS * EMB];
__device__ __nv_bfloat16  g_xl  [(size_t)ROWS * EMB];
__device__ __nv_bfloat16  g_wqh [(size_t)3 * EMB * EMB];
__device__ __nv_bfloat16  g_wql [(size_t)3 * EMB * EMB];
__device__ __nv_bfloat16  g_woh [(size_t)EMB * EMB];
__device__ __nv_bfloat16  g_wol [(size_t)EMB * EMB];
__device__ __half         g_qkv [(size_t)ROWS * 3 * EMB];   // fp16 q,k,v
__device__ __nv_bfloat16  g_ath [(size_t)ROWS * EMB];
__device__ __nv_bfloat16  g_atl [(size_t)ROWS * EMB];

// ---------------------------------------------------------------------------
__device__ __forceinline__ uint32_t smem_u32(const void* p) {
    uint32_t a;
    asm("{ .reg .u64 t; cvta.to.shared.u64 t, %1; cvt.u32.u64 %0, t; }"
        : "=r"(a) : "l"(p));
    return a;
}
__device__ __forceinline__ void cp_async16(uint32_t dst, const void* src) {
    asm volatile("cp.async.cg.shared.global [%0], [%1], 16;" :: "r"(dst), "l"(src));
}
__device__ __forceinline__ void cp_commit() { asm volatile("cp.async.commit_group;"); }
template<int N>
__device__ __forceinline__ void cp_wait() {
    asm volatile("cp.async.wait_group %0;" :: "n"(N));
}
__device__ __forceinline__ void ldsm_x4(uint32_t* r, uint32_t addr) {
    asm volatile("ldmatrix.sync.aligned.m8n8.x4.shared.b16 {%0,%1,%2,%3}, [%4];"
                 : "=r"(r[0]), "=r"(r[1]), "=r"(r[2]), "=r"(r[3]) : "r"(addr));
}
__device__ __forceinline__ void ldsm_x4t(uint32_t* r, uint32_t addr) {
    asm volatile("ldmatrix.sync.aligned.m8n8.x4.trans.shared.b16 {%0,%1,%2,%3}, [%4];"
                 : "=r"(r[0]), "=r"(r[1]), "=r"(r[2]), "=r"(r[3]) : "r"(addr));
}
__device__ __forceinline__ void mma_bf16(float* d, const uint32_t* a, const uint32_t* b) {
    asm volatile(
        "mma.sync.aligned.m16n8k16.row.col.f32.bf16.bf16.f32 "
        "{%0,%1,%2,%3}, {%4,%5,%6,%7}, {%8,%9}, {%0,%1,%2,%3};"
        : "+f"(d[0]), "+f"(d[1]), "+f"(d[2]), "+f"(d[3])
        : "r"(a[0]), "r"(a[1]), "r"(a[2]), "r"(a[3]), "r"(b[0]), "r"(b[1]));
}
__device__ __forceinline__ void mma_f16(float* d, const uint32_t* a, const uint32_t* b) {
    asm volatile(
        "mma.sync.aligned.m16n8k16.row.col.f32.f16.f16.f32 "
        "{%0,%1,%2,%3}, {%4,%5,%6,%7}, {%8,%9}, {%0,%1,%2,%3};"
        : "+f"(d[0]), "+f"(d[1]), "+f"(d[2]), "+f"(d[3])
        : "r"(a[0]), "r"(a[1]), "r"(a[2]), "r"(a[3]), "r"(b[0]), "r"(b[1]));
}
__device__ __forceinline__ uint32_t pack_h2(float x, float y) {
    __half2 h = __floats2half2_rn(x, y);
    return *(uint32_t*)&h;
}

// ---------------------------------------------------------------------------
// Fused fp32 -> bf16 (hi, lo) split for x, w_qkv, w_out in one launch.
// ---------------------------------------------------------------------------
#define XN   ((size_t)ROWS * EMB)
#define WQN  ((size_t)3 * EMB * EMB)
#define WON  ((size_t)EMB * EMB)
#define SPLIT_TOT (XN + WQN + WON)

__global__ __launch_bounds__(256)
void split_all(const float* __restrict__ x, const float* __restrict__ wq,
               const float* __restrict__ wo,
               __nv_bfloat16* __restrict__ xh, __nv_bfloat16* __restrict__ xl,
               __nv_bfloat16* __restrict__ wqh, __nv_bfloat16* __restrict__ wql,
               __nv_bfloat16* __restrict__ woh, __nv_bfloat16* __restrict__ wol)
{
    size_t i = ((size_t)blockIdx.x * 256 + threadIdx.x) * 4;
    const float* in; __nv_bfloat16 *hi, *lo; size_t off;
    if (i < XN)            { in = x;  hi = xh;  lo = xl;  off = i; }
    else if (i < XN + WQN) { in = wq; hi = wqh; lo = wql; off = i - XN; }
    else                   { in = wo; hi = woh; lo = wol; off = i - XN - WQN; }
    float4 v = *(const float4*)(in + off);
    __nv_bfloat162 h0 = __floats2bfloat162_rn(v.x, v.y);
    __nv_bfloat162 h1 = __floats2bfloat162_rn(v.z, v.w);
    __nv_bfloat162 l0 = __floats2bfloat162_rn(v.x - __low2float(h0), v.y - __high2float(h0));
    __nv_bfloat162 l1 = __floats2bfloat162_rn(v.z - __low2float(h1), v.w - __high2float(h1));
    *(__nv_bfloat162*)(hi + off)     = h0;
    *(__nv_bfloat162*)(hi + off + 2) = h1;
    *(__nv_bfloat162*)(lo + off)     = l0;
    *(__nv_bfloat162*)(lo + off + 2) = l1;
}

// ---------------------------------------------------------------------------
// 3-term bf16 split GEMM: C = A B^T. Output modes:
//   0: fp32 + bias    2: fp16 single
// CTA 128x128, 128 threads = 4 warps of 64x64. 3-stage cp.async pipeline,
// XOR-swizzled 128B rows (hi chunks 0-3, lo 4-7 at (chunk^(row&7))*16).
// ---------------------------------------------------------------------------
#define PAIR_B  16384
#define STG_B   (2 * PAIR_B)
#define GSMEM   (3 * STG_B)

template<int OUTM>
__global__ __launch_bounds__(128)
void gemm_mma(const __nv_bfloat16* __restrict__ Ah, const __nv_bfloat16* __restrict__ Al,
              const __nv_bfloat16* __restrict__ Bh, const __nv_bfloat16* __restrict__ Bl,
              const float* __restrict__ bias, float* __restrict__ C,
              __half* __restrict__ C16,
              int M, int N, int K)
{
    extern __shared__ char smem[];
    const uint32_t sbase = smem_u32(smem);

    const int t    = threadIdx.x;
    const int warp = t >> 5;
    const int lane = t & 31;
    const int wm   = warp >> 1;
    const int wn   = warp & 1;
    const int bm   = blockIdx.y * 128;
    const int bn   = blockIdx.x * 128;

    const int aRow = (lane & 15);
    const int aKh  = lane >> 4;
    const int bN   = ((lane >> 4) << 3) + (lane & 7);
    const int bKh  = (lane >> 3) & 1;

    float acc[4][8][4];
    #pragma unroll
    for (int i = 0; i < 4; i++)
        #pragma unroll
        for (int j = 0; j < 8; j++)
            #pragma unroll
            for (int r = 0; r < 4; r++) acc[i][j][r] = 0.f;

    const int nck = K >> 5;

    const int lchunk = t & 7;
    const int lrow   = t >> 3;
    auto load_chunk = [&](int ck, int stg) {
        const int ke = (ck << 5) + (lchunk & 3) * 8;
        #pragma unroll
        for (int it = 0; it < 16; it++) {
            const int pair = it >> 3;
            const int row  = (it & 7) * 16 + lrow;
            uint32_t dst = sbase + stg * STG_B + pair * PAIR_B
                         + row * 128 + ((lchunk ^ (row & 7)) << 4);
            const __nv_bfloat16* src;
            if (pair == 0) src = (lchunk < 4 ? Ah : Al) + (size_t)(bm + row) * K + ke;
            else           src = (lchunk < 4 ? Bh : Bl) + (size_t)(bn + row) * K + ke;
            cp_async16(dst, src);
        }
    };

    load_chunk(0, 0); cp_commit();
    load_chunk(1, 1); cp_commit();

    int stg = 0;
    for (int ck = 0; ck < nck; ck++) {
        if (ck + 1 < nck) cp_wait<1>(); else cp_wait<0>();
        __syncthreads();
        if (ck + 2 < nck) {
            int ns = stg + 2; if (ns >= 3) ns -= 3;
            load_chunk(ck + 2, ns); cp_commit();
        }

        const uint32_t stgb = sbase + stg * STG_B;
        #pragma unroll
        for (int ks = 0; ks < 2; ks++) {
            uint32_t ah[4][4], al[4][4], bh[8][2], bl[8][2];
            #pragma unroll
            for (int mi = 0; mi < 4; mi++) {
                const int row = wm * 64 + mi * 16 + aRow;
                const int ch  = ks * 2 + aKh;
                const uint32_t rb = stgb + row * 128;
                ldsm_x4(ah[mi], rb + ((ch       ^ (row & 7)) << 4));
                ldsm_x4(al[mi], rb + (((ch + 4) ^ (row & 7)) << 4));
            }
            #pragma unroll
            for (int p = 0; p < 4; p++) {
                const int row = wn * 64 + p * 16 + bN;
                const int ch  = ks * 2 + bKh;
                const uint32_t rb = stgb + PAIR_B + row * 128;
                uint32_t rh[4], rl[4];
                ldsm_x4(rh, rb + ((ch       ^ (row & 7)) << 4));
                ldsm_x4(rl, rb + (((ch + 4) ^ (row & 7)) << 4));
                bh[p * 2][0] = rh[0]; bh[p * 2][1] = rh[1];
                bh[p * 2 + 1][0] = rh[2]; bh[p * 2 + 1][1] = rh[3];
                bl[p * 2][0] = rl[0]; bl[p * 2][1] = rl[1];
                bl[p * 2 + 1][0] = rl[2]; bl[p * 2 + 1][1] = rl[3];
            }
            #pragma unroll
            for (int mi = 0; mi < 4; mi++)
                #pragma unroll
                for (int nj = 0; nj < 8; nj++) {
                    mma_bf16(acc[mi][nj], ah[mi], bh[nj]);
                    mma_bf16(acc[mi][nj], ah[mi], bl[nj]);
                    mma_bf16(acc[mi][nj], al[mi], bh[nj]);
                }
        }
        if (++stg == 3) stg = 0;
    }

    const int r0 = bm + wm * 64 + (lane >> 2);
    const int c0 = bn + wn * 64 + (lane & 3) * 2;
    #pragma unroll
    for (int mi = 0; mi < 4; mi++)
        #pragma unroll
        for (int nj = 0; nj < 8; nj++) {
            int row = r0 + mi * 16;
            int col = c0 + nj * 8;
            float2 v0 = make_float2(acc[mi][nj][0], acc[mi][nj][1]);
            float2 v1 = make_float2(acc[mi][nj][2], acc[mi][nj][3]);
            if (OUTM == 0) {
                v0.x += bias[col]; v0.y += bias[col + 1];
                v1.x += bias[col]; v1.y += bias[col + 1];
                *(float2*)(C + (size_t)row * N + col)       = v0;
                *(float2*)(C + (size_t)(row + 8) * N + col) = v1;
            } else {
                __half2 h0 = __floats2half2_rn(v0.x, v0.y);
                __half2 h1 = __floats2half2_rn(v1.x, v1.y);
                *(__half2*)(C16 + (size_t)row * N + col)       = h0;
                *(__half2*)(C16 + (size_t)(row + 8) * N + col) = h1;
            }
        }
}

// ---------------------------------------------------------------------------
// Flash attention, single-term fp16 mma. 3-stage KV pipeline (K,V per stage).
// qkv fp16 [4096][3072]; head h: q at h*192, k +64, v +128.
// Output bf16 hi/lo for the 3-term out-projection.
// ---------------------------------------------------------------------------
#define ATS    72                         // fp16 stride (64 + 8 pad)
#define QTILE  (128 * ATS * 2)            // 18432
#define KVT    (64 * ATS * 2)             // 9216
#define KVSTG  (2 * KVT)                  // 18432 (K, V)
#define ASMEM  (3 * KVSTG)                // 55296

__global__ __launch_bounds__(256)
void attn_mma(const __half* __restrict__ qkv,
              __nv_bfloat16* __restrict__ oh,
              __nv_bfloat16* __restrict__ ol)
{
    extern __shared__ char smem[];
    const uint32_t sbase = smem_u32(smem);

    const int t    = threadIdx.x;
    const int warp = t >> 5;
    const int lane = t & 31;
    const int qb   = 15 - blockIdx.x;
    const int h    = blockIdx.y;
    const int b    = blockIdx.z;
    const int wr0  = warp * 16;

    const int aRow = lane & 15;
    const int aKh  = lane >> 4;
    const int bN   = ((lane >> 4) << 3) + (lane & 7);
    const int bKh  = (lane >> 3) & 1;
    const int vRow = ((lane >> 3) & 1) * 8 + (lane & 7);
    const int vCol = (lane >> 4) * 8;

    const size_t qrow0 = (size_t)b * SEQ + qb * 128;

    // stage Q (fp16), build A-fragments, release smem
    #pragma unroll
    for (int it = 0; it < 4; it++) {
        const int linear = it * 256 + t;
        const int row = linear >> 3;
        const int kc  = (linear & 7) << 3;
        cp_async16(sbase + (row * ATS + kc) * 2,
                   qkv + (qrow0 + row) * 3072 + h * 192 + kc);
    }
    cp_commit();
    cp_wait<0>();
    __syncthreads();

    uint32_t qf[4][4];
    #pragma unroll
    for (int kt = 0; kt < 4; kt++) {
        ldsm_x4(qf[kt], sbase + ((wr0 + aRow) * ATS + kt * 16 + aKh * 8) * 2);
    }
    __syncthreads();

    float oacc[8][4];
    #pragma unroll
    for (int i = 0; i < 8; i++)
        #pragma unroll
        for (int j = 0; j < 4; j++) oacc[i][j] = 0.f;
    float m0 = -1e30f, m1 = -1e30f, l0 = 0.f, l1 = 0.f;

    const int r0g = qb * 128 + wr0 + (lane >> 2);
    const int r1g = r0g + 8;
    const int nblk = (qb + 1) * 2;

    auto load_kv = [&](int blk, int s) {
        const int j0 = blk * 64;
        const uint32_t kb = sbase + s * KVSTG;
        #pragma unroll
        for (int it = 0; it < 2; it++) {
            const int linear = it * 256 + t;
            const int row = linear >> 3;
            const int kc  = (linear & 7) << 3;
            uint32_t d = kb + (row * ATS + kc) * 2;
            const size_t gk = ((size_t)b * SEQ + j0 + row) * 3072 + h * 192 + 64 + kc;
            cp_async16(d,       qkv + gk);        // K
            cp_async16(d + KVT, qkv + gk + 64);   // V
        }
    };

    load_kv(0, 0); cp_commit();
    if (nblk > 1) { load_kv(1, 1); cp_commit(); }

    int stg = 0;
    for (int blk = 0; blk < nblk; blk++) {
        const int j0 = blk * 64;
        if (blk + 1 < nblk) cp_wait<1>(); else cp_wait<0>();
        __syncthreads();
        if (blk + 2 < nblk) {
            int ns = stg + 2; if (ns >= 3) ns -= 3;
            load_kv(blk + 2, ns); cp_commit();
        }

        const bool active = (j0 <= qb * 128 + wr0 + 15);
        if (active) {
            const uint32_t kb = sbase + stg * KVSTG;

            // ---- S = Q K^T (fp16 single-term)
            float sacc[8][4];
            #pragma unroll
            for (int i = 0; i < 8; i++)
                #pragma unroll
                for (int j = 0; j < 4; j++) sacc[i][j] = 0.f;
            #pragma unroll
            for (int kt = 0; kt < 4; kt++) {
                #pragma unroll
                for (int nt2 = 0; nt2 < 4; nt2++) {
                    uint32_t rk[4];
                    ldsm_x4(rk, kb + ((nt2 * 16 + bN) * ATS + kt * 16 + bKh * 8) * 2);
                    uint32_t k0[2] = {rk[0], rk[1]}, k1[2] = {rk[2], rk[3]};
                    mma_f16(sacc[nt2 * 2],     qf[kt], k0);
                    mma_f16(sacc[nt2 * 2 + 1], qf[kt], k1);
                }
            }

            // ---- causal mask
            if (j0 + 63 > qb * 128 + wr0) {
                #pragma unroll
                for (int nt = 0; nt < 8; nt++) {
                    const int c = j0 + nt * 8 + (lane & 3) * 2;
                    if (c     > r0g) sacc[nt][0] = -1e30f;
                    if (c + 1 > r0g) sacc[nt][1] = -1e30f;
                    if (c     > r1g) sacc[nt][2] = -1e30f;
                    if (c + 1 > r1g) sacc[nt][3] = -1e30f;
                }
            }

            // ---- online softmax (scale 0.125)
            float mx0 = -1e30f, mx1 = -1e30f;
            #pragma unroll
            for (int nt = 0; nt < 8; nt++) {
                mx0 = fmaxf(mx0, fmaxf(sacc[nt][0], sacc[nt][1]));
                mx1 = fmaxf(mx1, fmaxf(sacc[nt][2], sacc[nt][3]));
            }
            mx0 = fmaxf(mx0, __shfl_xor_sync(0xffffffffu, mx0, 1));
            mx0 = fmaxf(mx0, __shfl_xor_sync(0xffffffffu, mx0, 2));
            mx1 = fmaxf(mx1, __shfl_xor_sync(0xffffffffu, mx1, 1));
            mx1 = fmaxf(mx1, __shfl_xor_sync(0xffffffffu, mx1, 2));
            mx0 *= 0.125f; mx1 *= 0.125f;
            const float nm0 = fmaxf(m0, mx0), nm1 = fmaxf(m1, mx1);
            const float rs0 = __expf(m0 - nm0), rs1 = __expf(m1 - nm1);
            m0 = nm0; m1 = nm1;

            float sum0 = 0.f, sum1 = 0.f;
            #pragma unroll
            for (int nt = 0; nt < 8; nt++) {
                float p0 = __expf(fmaf(sacc[nt][0], 0.125f, -nm0));
                float p1 = __expf(fmaf(sacc[nt][1], 0.125f, -nm0));
                float p2 = __expf(fmaf(sacc[nt][2], 0.125f, -nm1));
                float p3 = __expf(fmaf(sacc[nt][3], 0.125f, -nm1));
                sacc[nt][0] = p0; sacc[nt][1] = p1;
                sacc[nt][2] = p2; sacc[nt][3] = p3;
                sum0 += p0 + p1; sum1 += p2 + p3;
            }
            sum0 += __shfl_xor_sync(0xffffffffu, sum0, 1);
            sum0 += __shfl_xor_sync(0xffffffffu, sum0, 2);
            sum1 += __shfl_xor_sync(0xffffffffu, sum1, 1);
            sum1 += __shfl_xor_sync(0xffffffffu, sum1, 2);
            l0 = l0 * rs0 + sum0;
            l1 = l1 * rs1 + sum1;

            #pragma unroll
            for (int dt = 0; dt < 8; dt++) {
                oacc[dt][0] *= rs0; oacc[dt][1] *= rs0;
                oacc[dt][2] *= rs1; oacc[dt][3] *= rs1;
            }

            // ---- O += P V (fp16 single-term)
            #pragma unroll
            for (int kt = 0; kt < 4; kt++) {
                uint32_t vf[8][2];
                #pragma unroll
                for (int dt2 = 0; dt2 < 4; dt2++) {
                    uint32_t rv[4];
                    ldsm_x4t(rv, kb + KVT + ((kt * 16 + vRow) * ATS + dt2 * 16 + vCol) * 2);
                    vf[dt2 * 2][0] = rv[0]; vf[dt2 * 2][1] = rv[1];
                    vf[dt2 * 2 + 1][0] = rv[2]; vf[dt2 * 2 + 1][1] = rv[3];
                }
                uint32_t Pa[4];
                #pragma unroll
                for (int half_ = 0; half_ < 2; half_++) {
                    const float* s = sacc[kt * 2 + half_];
                    Pa[half_ * 2]     = pack_h2(s[0], s[1]);
                    Pa[half_ * 2 + 1] = pack_h2(s[2], s[3]);
                }
                #pragma unroll
                for (int dt = 0; dt < 8; dt++)
                    mma_f16(oacc[dt], Pa, vf[dt]);
            }
        }
        if (++stg == 3) stg = 0;
    }

    // epilogue: normalize, bf16 hi/lo split for out-projection
    const float inv0 = 1.f / l0, inv1 = 1.f / l1;
    const size_t ro0 = (size_t)b * SEQ + qb * 128 + wr0 + (lane >> 2);
    const size_t ro1 = ro0 + 8;
    #pragma unroll
    for (int dt = 0; dt < 8; dt++) {
        const int col = h * 64 + dt * 8 + (lane & 3) * 2;
        float x0 = oacc[dt][0] * inv0, y0 = oacc[dt][1] * inv0;
        float x1 = oacc[dt][2] * inv1, y1 = oacc[dt][3] * inv1;
        __nv_bfloat162 h0 = __floats2bfloat162_rn(x0, y0);
        __nv_bfloat162 h1 = __floats2bfloat162_rn(x1, y1);
        __nv_bfloat162 e0 = __floats2bfloat162_rn(x0 - __low2float(h0), y0 - __high2float(h0));
        __nv_bfloat162 e1 = __floats2bfloat162_rn(x1 - __low2float(h1), y1 - __high2float(h1));
        *(__nv_bfloat162*)(oh + ro0 * EMB + col) = h0;
        *(__nv_bfloat162*)(oh + ro1 * EMB + col) = h1;
        *(__nv_bfloat162*)(ol + ro0 * EMB + col) = e0;
        *(__nv_bfloat162*)(ol + ro1 * EMB + col) = e1;
    }
}

// ---------------------------------------------------------------------------
extern "C" void kernel_launch(void* const* d_in, const int* in_sizes, int n_in,
                              void* d_out, int out_size)
{
    const float* x    = (const float*)d_in[0];
    const float* wqkv = (const float*)d_in[1];
    const float* wout = (const float*)d_in[2];
    const float* bout = (const float*)d_in[3];
    float* out = (float*)d_out;

    __nv_bfloat16 *xh, *xl, *wqh, *wql, *woh, *wol, *ath, *atl;
    __half* qkv16;
    cudaGetSymbolAddress((void**)&xh,    g_xh);
    cudaGetSymbolAddress((void**)&xl,    g_xl);
    cudaGetSymbolAddress((void**)&wqh,   g_wqh);
    cudaGetSymbolAddress((void**)&wql,   g_wql);
    cudaGetSymbolAddress((void**)&woh,   g_woh);
    cudaGetSymbolAddress((void**)&wol,   g_wol);
    cudaGetSymbolAddress((void**)&qkv16, g_qkv);
    cudaGetSymbolAddress((void**)&ath,   g_ath);
    cudaGetSymbolAddress((void**)&atl,   g_atl);

    cudaFuncSetAttribute(gemm_mma<2>,
                         cudaFuncAttributeMaxDynamicSharedMemorySize, GSMEM);
    cudaFuncSetAttribute(gemm_mma<0>,
                         cudaFuncAttributeMaxDynamicSharedMemorySize, GSMEM);
    cudaFuncSetAttribute(attn_mma,
                         cudaFuncAttributeMaxDynamicSharedMemorySize, ASMEM);

    split_all<<<SPLIT_TOT / 1024, 256>>>(x, wqkv, wout,
                                         xh, xl, wqh, wql, woh, wol);

    // 1) QKV projection (3-term bf16) -> fp16 q,k,v
    gemm_mma<2><<<dim3(3072 / 128, ROWS / 128), 128, GSMEM>>>(
        xh, xl, wqh, wql, nullptr, nullptr, qkv16, ROWS, 3072, EMB);

    // 2) causal flash attention (fp16 single-term) -> bf16 hi/lo
    attn_mma<<<dim3(SEQ / 128, NH, 2), 256, ASMEM>>>(qkv16, ath, atl);

    // 3) out projection + bias (3-term bf16) -> fp32
    gemm_mma<0><<<dim3(EMB / 128, ROWS / 128), 128, GSMEM>>>(
        ath, atl, woh, wol, bout, out, nullptr, ROWS, EMB, EMB);
}

// round 10
// speedup vs baseline: 1.7775x; 1.2314x over previous
#include <cuda_runtime.h>
#include <cuda_bf16.h>
#include <cuda_fp16.h>
#include <cstdint>

// ---------------------------------------------------------------------------
// bs=2, seq=2048, embed=1024, heads=16, head_dim=64
// R10: everything fp16 tensor-core.
//   activations: single fp16 (rounding ~2^-11, calibrated ~1.8e-4 each)
//   weights: 2-term fp16 split (Wh + Wl, residual ~2^-22)
//   projections: 2 MMAs/tile; attention interior: 1 MMA (unchanged from R9)
// ---------------------------------------------------------------------------

#define SEQ   2048
#define EMB   1024
#define NH    16
#define HD    64
#define ROWS  4096

__device__ __half  g_x16 [(size_t)ROWS * EMB];
__device__ __half  g_wqh [(size_t)3 * EMB * EMB];
__device__ __half  g_wql [(size_t)3 * EMB * EMB];
__device__ __half  g_woh [(size_t)EMB * EMB];
__device__ __half  g_wol [(size_t)EMB * EMB];
__device__ __half  g_qkv [(size_t)ROWS * 3 * EMB];
__device__ __half  g_att [(size_t)ROWS * EMB];

// ---------------------------------------------------------------------------
__device__ __forceinline__ uint32_t smem_u32(const void* p) {
    uint32_t a;
    asm("{ .reg .u64 t; cvta.to.shared.u64 t, %1; cvt.u32.u64 %0, t; }"
        : "=r"(a) : "l"(p));
    return a;
}
__device__ __forceinline__ void cp_async16(uint32_t dst, const void* src) {
    asm volatile("cp.async.cg.shared.global [%0], [%1], 16;" :: "r"(dst), "l"(src));
}
__device__ __forceinline__ void cp_commit() { asm volatile("cp.async.commit_group;"); }
template<int N>
__device__ __forceinline__ void cp_wait() {
    asm volatile("cp.async.wait_group %0;" :: "n"(N));
}
__device__ __forceinline__ void ldsm_x4(uint32_t* r, uint32_t addr) {
    asm volatile("ldmatrix.sync.aligned.m8n8.x4.shared.b16 {%0,%1,%2,%3}, [%4];"
                 : "=r"(r[0]), "=r"(r[1]), "=r"(r[2]), "=r"(r[3]) : "r"(addr));
}
__device__ __forceinline__ void ldsm_x4t(uint32_t* r, uint32_t addr) {
    asm volatile("ldmatrix.sync.aligned.m8n8.x4.trans.shared.b16 {%0,%1,%2,%3}, [%4];"
                 : "=r"(r[0]), "=r"(r[1]), "=r"(r[2]), "=r"(r[3]) : "r"(addr));
}
__device__ __forceinline__ void mma_f16(float* d, const uint32_t* a, const uint32_t* b) {
    asm volatile(
        "mma.sync.aligned.m16n8k16.row.col.f32.f16.f16.f32 "
        "{%0,%1,%2,%3}, {%4,%5,%6,%7}, {%8,%9}, {%0,%1,%2,%3};"
        : "+f"(d[0]), "+f"(d[1]), "+f"(d[2]), "+f"(d[3])
        : "r"(a[0]), "r"(a[1]), "r"(a[2]), "r"(a[3]), "r"(b[0]), "r"(b[1]));
}
__device__ __forceinline__ uint32_t pack_h2(float x, float y) {
    __half2 h = __floats2half2_rn(x, y);
    return *(uint32_t*)&h;
}

// ---------------------------------------------------------------------------
// Fused conversion: x -> fp16 single; w_qkv, w_out -> fp16 (hi, lo) split.
// ---------------------------------------------------------------------------
#define XN   ((size_t)ROWS * EMB)
#define WQN  ((size_t)3 * EMB * EMB)
#define WON  ((size_t)EMB * EMB)
#define SPLIT_TOT (XN + WQN + WON)

__global__ __launch_bounds__(256)
void split_all(const float* __restrict__ x, const float* __restrict__ wq,
               const float* __restrict__ wo,
               __half* __restrict__ x16,
               __half* __restrict__ wqh, __half* __restrict__ wql,
               __half* __restrict__ woh, __half* __restrict__ wol)
{
    size_t i = ((size_t)blockIdx.x * 256 + threadIdx.x) * 4;
    if (i < XN) {
        float4 v = *(const float4*)(x + i);
        *(__half2*)(x16 + i)     = __floats2half2_rn(v.x, v.y);
        *(__half2*)(x16 + i + 2) = __floats2half2_rn(v.z, v.w);
        return;
    }
    const float* in; __half *hi, *lo; size_t off;
    if (i < XN + WQN) { in = wq; hi = wqh; lo = wql; off = i - XN; }
    else              { in = wo; hi = woh; lo = wol; off = i - XN - WQN; }
    float4 v = *(const float4*)(in + off);
    __half2 h0 = __floats2half2_rn(v.x, v.y);
    __half2 h1 = __floats2half2_rn(v.z, v.w);
    __half2 l0 = __floats2half2_rn(v.x - __low2float(h0), v.y - __high2float(h0));
    __half2 l1 = __floats2half2_rn(v.z - __low2float(h1), v.w - __high2float(h1));
    *(__half2*)(hi + off)     = h0;
    *(__half2*)(hi + off + 2) = h1;
    *(__half2*)(lo + off)     = l0;
    *(__half2*)(lo + off + 2) = l1;
}

// ---------------------------------------------------------------------------
// fp16 GEMM, 2-term weights: C = A (Bh + Bl)^T. Output 0: fp32+bias, 2: fp16.
// CTA 128x128, 128 threads = 4 warps of 64x64. 3-stage cp.async pipeline.
// Smem: per stage 2 "pairs" of 128 rows x 128B. Logical chunk c (16B) of a
// row lives at physical slot (c ^ (row&7)). A uses logical chunks 0-3 only
// (physical slots scattered by the XOR; other half dead). B: hi 0-3, lo 4-7.
// ---------------------------------------------------------------------------
#define PAIR_B  16384
#define STG_B   (2 * PAIR_B)
#define GSMEM   (3 * STG_B)              // 98304

template<int OUTM>
__global__ __launch_bounds__(128)
void gemm_f16(const __half* __restrict__ A,
              const __half* __restrict__ Bh, const __half* __restrict__ Bl,
              const float* __restrict__ bias, float* __restrict__ C,
              __half* __restrict__ C16,
              int M, int N, int K)
{
    extern __shared__ char smem[];
    const uint32_t sbase = smem_u32(smem);

    const int t    = threadIdx.x;
    const int warp = t >> 5;
    const int lane = t & 31;
    const int wm   = warp >> 1;
    const int wn   = warp & 1;
    const int bm   = blockIdx.y * 128;
    const int bn   = blockIdx.x * 128;

    const int aRow = (lane & 15);
    const int aKh  = lane >> 4;
    const int bN   = ((lane >> 4) << 3) + (lane & 7);
    const int bKh  = (lane >> 3) & 1;

    float acc[4][8][4];
    #pragma unroll
    for (int i = 0; i < 4; i++)
        #pragma unroll
        for (int j = 0; j < 8; j++)
            #pragma unroll
            for (int r = 0; r < 4; r++) acc[i][j][r] = 0.f;

    const int nck = K >> 5;

    const int lchunk = t & 7;             // B: 0-7 (hi/lo). A: only 0-3 load.
    const int lrow   = t >> 3;            // 0..15
    auto load_chunk = [&](int ck, int stg) {
        const int ke = (ck << 5) + (lchunk & 3) * 8;
        // B tile: 8 iterations x 128 threads x 16B = 16 KB
        #pragma unroll
        for (int it = 0; it < 8; it++) {
            const int row = it * 16 + lrow;
            uint32_t dst = sbase + stg * STG_B + PAIR_B
                         + row * 128 + ((lchunk ^ (row & 7)) << 4);
            const __half* src = (lchunk < 4 ? Bh : Bl) + (size_t)(bn + row) * K + ke;
            cp_async16(dst, src);
        }
        // A tile: logical chunks 0-3 only (threads with lchunk<4), 8 KB
        if (lchunk < 4) {
            #pragma unroll
            for (int it = 0; it < 8; it++) {
                const int row = it * 16 + lrow;
                uint32_t dst = sbase + stg * STG_B
                             + row * 128 + ((lchunk ^ (row & 7)) << 4);
                cp_async16(dst, A + (size_t)(bm + row) * K + ke);
            }
        }
    };

    load_chunk(0, 0); cp_commit();
    load_chunk(1, 1); cp_commit();

    int stg = 0;
    for (int ck = 0; ck < nck; ck++) {
        if (ck + 1 < nck) cp_wait<1>(); else cp_wait<0>();
        __syncthreads();
        if (ck + 2 < nck) {
            int ns = stg + 2; if (ns >= 3) ns -= 3;
            load_chunk(ck + 2, ns); cp_commit();
        }

        const uint32_t stgb = sbase + stg * STG_B;
        #pragma unroll
        for (int ks = 0; ks < 2; ks++) {
            uint32_t af[4][4], bh[8][2], bl[8][2];
            #pragma unroll
            for (int mi = 0; mi < 4; mi++) {
                const int row = wm * 64 + mi * 16 + aRow;
                const int ch  = ks * 2 + aKh;
                ldsm_x4(af[mi], stgb + row * 128 + ((ch ^ (row & 7)) << 4));
            }
            #pragma unroll
            for (int p = 0; p < 4; p++) {
                const int row = wn * 64 + p * 16 + bN;
                const int ch  = ks * 2 + bKh;
                const uint32_t rb = stgb + PAIR_B + row * 128;
                uint32_t rh[4], rl[4];
                ldsm_x4(rh, rb + ((ch       ^ (row & 7)) << 4));
                ldsm_x4(rl, rb + (((ch + 4) ^ (row & 7)) << 4));
                bh[p * 2][0] = rh[0]; bh[p * 2][1] = rh[1];
                bh[p * 2 + 1][0] = rh[2]; bh[p * 2 + 1][1] = rh[3];
                bl[p * 2][0] = rl[0]; bl[p * 2][1] = rl[1];
                bl[p * 2 + 1][0] = rl[2]; bl[p * 2 + 1][1] = rl[3];
            }
            #pragma unroll
            for (int mi = 0; mi < 4; mi++)
                #pragma unroll
                for (int nj = 0; nj < 8; nj++) {
                    mma_f16(acc[mi][nj], af[mi], bh[nj]);
                    mma_f16(acc[mi][nj], af[mi], bl[nj]);
                }
        }
        if (++stg == 3) stg = 0;
    }

    const int r0 = bm + wm * 64 + (lane >> 2);
    const int c0 = bn + wn * 64 + (lane & 3) * 2;
    #pragma unroll
    for (int mi = 0; mi < 4; mi++)
        #pragma unroll
        for (int nj = 0; nj < 8; nj++) {
            int row = r0 + mi * 16;
            int col = c0 + nj * 8;
            float2 v0 = make_float2(acc[mi][nj][0], acc[mi][nj][1]);
            float2 v1 = make_float2(acc[mi][nj][2], acc[mi][nj][3]);
            if (OUTM == 0) {
                v0.x += bias[col]; v0.y += bias[col + 1];
                v1.x += bias[col]; v1.y += bias[col + 1];
                *(float2*)(C + (size_t)row * N + col)       = v0;
                *(float2*)(C + (size_t)(row + 8) * N + col) = v1;
            } else {
                *(__half2*)(C16 + (size_t)row * N + col)       = __floats2half2_rn(v0.x, v0.y);
                *(__half2*)(C16 + (size_t)(row + 8) * N + col) = __floats2half2_rn(v1.x, v1.y);
            }
        }
}

// ---------------------------------------------------------------------------
// Flash attention, single-term fp16 mma. 3-stage KV pipeline (K,V per stage).
// qkv fp16 [4096][3072]; head h: q at h*192, k +64, v +128. Output fp16.
// ---------------------------------------------------------------------------
#define ATS    72
#define QTILE  (128 * ATS * 2)
#define KVT    (64 * ATS * 2)
#define KVSTG  (2 * KVT)
#define ASMEM  (3 * KVSTG)

__global__ __launch_bounds__(256)
void attn_mma(const __half* __restrict__ qkv, __half* __restrict__ o16)
{
    extern __shared__ char smem[];
    const uint32_t sbase = smem_u32(smem);

    const int t    = threadIdx.x;
    const int warp = t >> 5;
    const int lane = t & 31;
    const int qb   = 15 - blockIdx.x;
    const int h    = blockIdx.y;
    const int b    = blockIdx.z;
    const int wr0  = warp * 16;

    const int aRow = lane & 15;
    const int aKh  = lane >> 4;
    const int bN   = ((lane >> 4) << 3) + (lane & 7);
    const int bKh  = (lane >> 3) & 1;
    const int vRow = ((lane >> 3) & 1) * 8 + (lane & 7);
    const int vCol = (lane >> 4) * 8;

    const size_t qrow0 = (size_t)b * SEQ + qb * 128;

    #pragma unroll
    for (int it = 0; it < 4; it++) {
        const int linear = it * 256 + t;
        const int row = linear >> 3;
        const int kc  = (linear & 7) << 3;
        cp_async16(sbase + (row * ATS + kc) * 2,
                   qkv + (qrow0 + row) * 3072 + h * 192 + kc);
    }
    cp_commit();
    cp_wait<0>();
    __syncthreads();

    uint32_t qf[4][4];
    #pragma unroll
    for (int kt = 0; kt < 4; kt++)
        ldsm_x4(qf[kt], sbase + ((wr0 + aRow) * ATS + kt * 16 + aKh * 8) * 2);
    __syncthreads();

    float oacc[8][4];
    #pragma unroll
    for (int i = 0; i < 8; i++)
        #pragma unroll
        for (int j = 0; j < 4; j++) oacc[i][j] = 0.f;
    float m0 = -1e30f, m1 = -1e30f, l0 = 0.f, l1 = 0.f;

    const int r0g = qb * 128 + wr0 + (lane >> 2);
    const int r1g = r0g + 8;
    const int nblk = (qb + 1) * 2;

    auto load_kv = [&](int blk, int s) {
        const int j0 = blk * 64;
        const uint32_t kb = sbase + s * KVSTG;
        #pragma unroll
        for (int it = 0; it < 2; it++) {
            const int linear = it * 256 + t;
            const int row = linear >> 3;
            const int kc  = (linear & 7) << 3;
            uint32_t d = kb + (row * ATS + kc) * 2;
            const size_t gk = ((size_t)b * SEQ + j0 + row) * 3072 + h * 192 + 64 + kc;
            cp_async16(d,       qkv + gk);
            cp_async16(d + KVT, qkv + gk + 64);
        }
    };

    load_kv(0, 0); cp_commit();
    if (nblk > 1) { load_kv(1, 1); cp_commit(); }

    int stg = 0;
    for (int blk = 0; blk < nblk; blk++) {
        const int j0 = blk * 64;
        if (blk + 1 < nblk) cp_wait<1>(); else cp_wait<0>();
        __syncthreads();
        if (blk + 2 < nblk) {
            int ns = stg + 2; if (ns >= 3) ns -= 3;
            load_kv(blk + 2, ns); cp_commit();
        }

        const bool active = (j0 <= qb * 128 + wr0 + 15);
        if (active) {
            const uint32_t kb = sbase + stg * KVSTG;

            float sacc[8][4];
            #pragma unroll
            for (int i = 0; i < 8; i++)
                #pragma unroll
                for (int j = 0; j < 4; j++) sacc[i][j] = 0.f;
            #pragma unroll
            for (int kt = 0; kt < 4; kt++) {
                #pragma unroll
                for (int nt2 = 0; nt2 < 4; nt2++) {
                    uint32_t rk[4];
                    ldsm_x4(rk, kb + ((nt2 * 16 + bN) * ATS + kt * 16 + bKh * 8) * 2);
                    uint32_t k0[2] = {rk[0], rk[1]}, k1[2] = {rk[2], rk[3]};
                    mma_f16(sacc[nt2 * 2],     qf[kt], k0);
                    mma_f16(sacc[nt2 * 2 + 1], qf[kt], k1);
                }
            }

            if (j0 + 63 > qb * 128 + wr0) {
                #pragma unroll
                for (int nt = 0; nt < 8; nt++) {
                    const int c = j0 + nt * 8 + (lane & 3) * 2;
                    if (c     > r0g) sacc[nt][0] = -1e30f;
                    if (c + 1 > r0g) sacc[nt][1] = -1e30f;
                    if (c     > r1g) sacc[nt][2] = -1e30f;
                    if (c + 1 > r1g) sacc[nt][3] = -1e30f;
                }
            }

            float mx0 = -1e30f, mx1 = -1e30f;
            #pragma unroll
            for (int nt = 0; nt < 8; nt++) {
                mx0 = fmaxf(mx0, fmaxf(sacc[nt][0], sacc[nt][1]));
                mx1 = fmaxf(mx1, fmaxf(sacc[nt][2], sacc[nt][3]));
            }
            mx0 = fmaxf(mx0, __shfl_xor_sync(0xffffffffu, mx0, 1));
            mx0 = fmaxf(mx0, __shfl_xor_sync(0xffffffffu, mx0, 2));
            mx1 = fmaxf(mx1, __shfl_xor_sync(0xffffffffu, mx1, 1));
            mx1 = fmaxf(mx1, __shfl_xor_sync(0xffffffffu, mx1, 2));
            mx0 *= 0.125f; mx1 *= 0.125f;
            const float nm0 = fmaxf(m0, mx0), nm1 = fmaxf(m1, mx1);
            const float rs0 = __expf(m0 - nm0), rs1 = __expf(m1 - nm1);
            m0 = nm0; m1 = nm1;

            float sum0 = 0.f, sum1 = 0.f;
            #pragma unroll
            for (int nt = 0; nt < 8; nt++) {
                float p0 = __expf(fmaf(sacc[nt][0], 0.125f, -nm0));
                float p1 = __expf(fmaf(sacc[nt][1], 0.125f, -nm0));
                float p2 = __expf(fmaf(sacc[nt][2], 0.125f, -nm1));
                float p3 = __expf(fmaf(sacc[nt][3], 0.125f, -nm1));
                sacc[nt][0] = p0; sacc[nt][1] = p1;
                sacc[nt][2] = p2; sacc[nt][3] = p3;
                sum0 += p0 + p1; sum1 += p2 + p3;
            }
            sum0 += __shfl_xor_sync(0xffffffffu, sum0, 1);
            sum0 += __shfl_xor_sync(0xffffffffu, sum0, 2);
            sum1 += __shfl_xor_sync(0xffffffffu, sum1, 1);
            sum1 += __shfl_xor_sync(0xffffffffu, sum1, 2);
            l0 = l0 * rs0 + sum0;
            l1 = l1 * rs1 + sum1;

            #pragma unroll
            for (int dt = 0; dt < 8; dt++) {
                oacc[dt][0] *= rs0; oacc[dt][1] *= rs0;
                oacc[dt][2] *= rs1; oacc[dt][3] *= rs1;
            }

            #pragma unroll
            for (int kt = 0; kt < 4; kt++) {
                uint32_t vf[8][2];
                #pragma unroll
                for (int dt2 = 0; dt2 < 4; dt2++) {
                    uint32_t rv[4];
                    ldsm_x4t(rv, kb + KVT + ((kt * 16 + vRow) * ATS + dt2 * 16 + vCol) * 2);
                    vf[dt2 * 2][0] = rv[0]; vf[dt2 * 2][1] = rv[1];
                    vf[dt2 * 2 + 1][0] = rv[2]; vf[dt2 * 2 + 1][1] = rv[3];
                }
                uint32_t Pa[4];
                #pragma unroll
                for (int half_ = 0; half_ < 2; half_++) {
                    const float* s = sacc[kt * 2 + half_];
                    Pa[half_ * 2]     = pack_h2(s[0], s[1]);
                    Pa[half_ * 2 + 1] = pack_h2(s[2], s[3]);
                }
                #pragma unroll
                for (int dt = 0; dt < 8; dt++)
                    mma_f16(oacc[dt], Pa, vf[dt]);
            }
        }
        if (++stg == 3) stg = 0;
    }

    const float inv0 = 1.f / l0, inv1 = 1.f / l1;
    const size_t ro0 = (size_t)b * SEQ + qb * 128 + wr0 + (lane >> 2);
    const size_t ro1 = ro0 + 8;
    #pragma unroll
    for (int dt = 0; dt < 8; dt++) {
        const int col = h * 64 + dt * 8 + (lane & 3) * 2;
        *(__half2*)(o16 + ro0 * EMB + col) =
            __floats2half2_rn(oacc[dt][0] * inv0, oacc[dt][1] * inv0);
        *(__half2*)(o16 + ro1 * EMB + col) =
            __floats2half2_rn(oacc[dt][2] * inv1, oacc[dt][3] * inv1);
    }
}

// ---------------------------------------------------------------------------
extern "C" void kernel_launch(void* const* d_in, const int* in_sizes, int n_in,
                              void* d_out, int out_size)
{
    const float* x    = (const float*)d_in[0];
    const float* wqkv = (const float*)d_in[1];
    const float* wout = (const float*)d_in[2];
    const float* bout = (const float*)d_in[3];
    float* out = (float*)d_out;

    __half *x16, *wqh, *wql, *woh, *wol, *qkv16, *att16;
    cudaGetSymbolAddress((void**)&x16,   g_x16);
    cudaGetSymbolAddress((void**)&wqh,   g_wqh);
    cudaGetSymbolAddress((void**)&wql,   g_wql);
    cudaGetSymbolAddress((void**)&woh,   g_woh);
    cudaGetSymbolAddress((void**)&wol,   g_wol);
    cudaGetSymbolAddress((void**)&qkv16, g_qkv);
    cudaGetSymbolAddress((void**)&att16, g_att);

    cudaFuncSetAttribute(gemm_f16<2>,
                         cudaFuncAttributeMaxDynamicSharedMemorySize, GSMEM);
    cudaFuncSetAttribute(gemm_f16<0>,
                         cudaFuncAttributeMaxDynamicSharedMemorySize, GSMEM);
    cudaFuncSetAttribute(attn_mma,
                         cudaFuncAttributeMaxDynamicSharedMemorySize, ASMEM);

    // 0) conversions (one launch)
    split_all<<<SPLIT_TOT / 1024, 256>>>(x, wqkv, wout,
                                         x16, wqh, wql, woh, wol);

    // 1) QKV projection (fp16, 2-term weights) -> fp16 q,k,v
    gemm_f16<2><<<dim3(3072 / 128, ROWS / 128), 128, GSMEM>>>(
        x16, wqh, wql, nullptr, nullptr, qkv16, ROWS, 3072, EMB);

    // 2) causal flash attention (fp16) -> fp16
    attn_mma<<<dim3(SEQ / 128, NH, 2), 256, ASMEM>>>(qkv16, att16);

    // 3) out projection + bias (fp16, 2-term weights) -> fp32
    gemm_f16<0><<<dim3(EMB / 128, ROWS / 128), 128, GSMEM>>>(
        att16, woh, wol, bout, out, nullptr, ROWS, EMB, EMB);
}

// round 12
// speedup vs baseline: 1.7905x; 1.0073x over previous
#include <cuda_runtime.h>
#include <cuda_bf16.h>
#include <cuda_fp16.h>
#include <cstdint>

// ---------------------------------------------------------------------------
// bs=2, seq=2048, embed=1024, heads=16, head_dim=64
// R11: same math as R10 (fp16 activations, 2-term fp16 weights, fp16 attn).
//      GEMMs: 2-stage pipeline (64KB smem) + __launch_bounds__(128,3)
//      -> 3 CTAs/SM = 12 warps/SM (was 8); latency-bound fix.
// ---------------------------------------------------------------------------

#define SEQ   2048
#define EMB   1024
#define NH    16
#define HD    64
#define ROWS  4096

__device__ __half  g_x16 [(size_t)ROWS * EMB];
__device__ __half  g_wqh [(size_t)3 * EMB * EMB];
__device__ __half  g_wql [(size_t)3 * EMB * EMB];
__device__ __half  g_woh [(size_t)EMB * EMB];
__device__ __half  g_wol [(size_t)EMB * EMB];
__device__ __half  g_qkv [(size_t)ROWS * 3 * EMB];
__device__ __half  g_att [(size_t)ROWS * EMB];

// ---------------------------------------------------------------------------
__device__ __forceinline__ uint32_t smem_u32(const void* p) {
    uint32_t a;
    asm("{ .reg .u64 t; cvta.to.shared.u64 t, %1; cvt.u32.u64 %0, t; }"
        : "=r"(a) : "l"(p));
    return a;
}
__device__ __forceinline__ void cp_async16(uint32_t dst, const void* src) {
    asm volatile("cp.async.cg.shared.global [%0], [%1], 16;" :: "r"(dst), "l"(src));
}
__device__ __forceinline__ void cp_commit() { asm volatile("cp.async.commit_group;"); }
template<int N>
__device__ __forceinline__ void cp_wait() {
    asm volatile("cp.async.wait_group %0;" :: "n"(N));
}
__device__ __forceinline__ void ldsm_x4(uint32_t* r, uint32_t addr) {
    asm volatile("ldmatrix.sync.aligned.m8n8.x4.shared.b16 {%0,%1,%2,%3}, [%4];"
                 : "=r"(r[0]), "=r"(r[1]), "=r"(r[2]), "=r"(r[3]) : "r"(addr));
}
__device__ __forceinline__ void ldsm_x4t(uint32_t* r, uint32_t addr) {
    asm volatile("ldmatrix.sync.aligned.m8n8.x4.trans.shared.b16 {%0,%1,%2,%3}, [%4];"
                 : "=r"(r[0]), "=r"(r[1]), "=r"(r[2]), "=r"(r[3]) : "r"(addr));
}
__device__ __forceinline__ void mma_f16(float* d, const uint32_t* a, const uint32_t* b) {
    asm volatile(
        "mma.sync.aligned.m16n8k16.row.col.f32.f16.f16.f32 "
        "{%0,%1,%2,%3}, {%4,%5,%6,%7}, {%8,%9}, {%0,%1,%2,%3};"
        : "+f"(d[0]), "+f"(d[1]), "+f"(d[2]), "+f"(d[3])
        : "r"(a[0]), "r"(a[1]), "r"(a[2]), "r"(a[3]), "r"(b[0]), "r"(b[1]));
}
__device__ __forceinline__ uint32_t pack_h2(float x, float y) {
    __half2 h = __floats2half2_rn(x, y);
    return *(uint32_t*)&h;
}

// ---------------------------------------------------------------------------
// Fused conversion: x -> fp16; w_qkv, w_out -> fp16 (hi, lo) split.
// ---------------------------------------------------------------------------
#define XN   ((size_t)ROWS * EMB)
#define WQN  ((size_t)3 * EMB * EMB)
#define WON  ((size_t)EMB * EMB)
#define SPLIT_TOT (XN + WQN + WON)

__global__ __launch_bounds__(256)
void split_all(const float* __restrict__ x, const float* __restrict__ wq,
               const float* __restrict__ wo,
               __half* __restrict__ x16,
               __half* __restrict__ wqh, __half* __restrict__ wql,
               __half* __restrict__ woh, __half* __restrict__ wol)
{
    size_t i = ((size_t)blockIdx.x * 256 + threadIdx.x) * 4;
    if (i < XN) {
        float4 v = *(const float4*)(x + i);
        *(__half2*)(x16 + i)     = __floats2half2_rn(v.x, v.y);
        *(__half2*)(x16 + i + 2) = __floats2half2_rn(v.z, v.w);
        return;
    }
    const float* in; __half *hi, *lo; size_t off;
    if (i < XN + WQN) { in = wq; hi = wqh; lo = wql; off = i - XN; }
    else              { in = wo; hi = woh; lo = wol; off = i - XN - WQN; }
    float4 v = *(const float4*)(in + off);
    __half2 h0 = __floats2half2_rn(v.x, v.y);
    __half2 h1 = __floats2half2_rn(v.z, v.w);
    __half2 l0 = __floats2half2_rn(v.x - __low2float(h0), v.y - __high2float(h0));
    __half2 l1 = __floats2half2_rn(v.z - __low2float(h1), v.w - __high2float(h1));
    *(__half2*)(hi + off)     = h0;
    *(__half2*)(hi + off + 2) = h1;
    *(__half2*)(lo + off)     = l0;
    *(__half2*)(lo + off + 2) = l1;
}

// ---------------------------------------------------------------------------
// fp16 GEMM, 2-term weights: C = A (Bh + Bl)^T. Output 0: fp32+bias, 2: fp16.
// CTA 128x128, 128 threads = 4 warps of 64x64.
// 2-stage cp.async pipeline (2 syncs/chunk), 3 CTAs/SM via launch_bounds.
// Smem/stage: A pair + B pair, 128 rows x 128B, slot (chunk ^ (row&7))*16.
// A uses logical chunks 0-3; B: hi 0-3, lo 4-7.
// ---------------------------------------------------------------------------
#define PAIR_B  16384
#define STG_B   (2 * PAIR_B)             // 32768
#define GSMEM   (2 * STG_B)              // 65536 -> 3 CTAs/SM

template<int OUTM>
__global__ __launch_bounds__(128, 3)
void gemm_f16(const __half* __restrict__ A,
              const __half* __restrict__ Bh, const __half* __restrict__ Bl,
              const float* __restrict__ bias, float* __restrict__ C,
              __half* __restrict__ C16,
              int M, int N, int K)
{
    extern __shared__ char smem[];
    const uint32_t sbase = smem_u32(smem);

    const int t    = threadIdx.x;
    const int warp = t >> 5;
    const int lane = t & 31;
    const int wm   = warp >> 1;
    const int wn   = warp & 1;
    const int bm   = blockIdx.y * 128;
    const int bn   = blockIdx.x * 128;

    const int aRow = (lane & 15);
    const int aKh  = lane >> 4;
    const int bN   = ((lane >> 4) << 3) + (lane & 7);
    const int bKh  = (lane >> 3) & 1;

    float acc[4][8][4];
    #pragma unroll
    for (int i = 0; i < 4; i++)
        #pragma unroll
        for (int j = 0; j < 8; j++)
            #pragma unroll
            for (int r = 0; r < 4; r++) acc[i][j][r] = 0.f;

    const int nck = K >> 5;

    const int lchunk = t & 7;
    const int lrow   = t >> 3;
    auto load_chunk = [&](int ck, int stg) {
        const int ke = (ck << 5) + (lchunk & 3) * 8;
        #pragma unroll
        for (int it = 0; it < 8; it++) {
            const int row = it * 16 + lrow;
            uint32_t dst = sbase + stg * STG_B + PAIR_B
                         + row * 128 + ((lchunk ^ (row & 7)) << 4);
            const __half* src = (lchunk < 4 ? Bh : Bl) + (size_t)(bn + row) * K + ke;
            cp_async16(dst, src);
        }
        if (lchunk < 4) {
            #pragma unroll
            for (int it = 0; it < 8; it++) {
                const int row = it * 16 + lrow;
                uint32_t dst = sbase + stg * STG_B
                             + row * 128 + ((lchunk ^ (row & 7)) << 4);
                cp_async16(dst, A + (size_t)(bm + row) * K + ke);
            }
        }
    };

    load_chunk(0, 0); cp_commit();

    for (int ck = 0; ck < nck; ck++) {
        if (ck + 1 < nck) {
            load_chunk(ck + 1, (ck + 1) & 1); cp_commit(); cp_wait<1>();
        } else {
            cp_wait<0>();
        }
        __syncthreads();

        const uint32_t stgb = sbase + (ck & 1) * STG_B;
        #pragma unroll
        for (int ks = 0; ks < 2; ks++) {
            uint32_t af[4][4], bh[8][2], bl[8][2];
            #pragma unroll
            for (int mi = 0; mi < 4; mi++) {
                const int row = wm * 64 + mi * 16 + aRow;
                const int ch  = ks * 2 + aKh;
                ldsm_x4(af[mi], stgb + row * 128 + ((ch ^ (row & 7)) << 4));
            }
            #pragma unroll
            for (int p = 0; p < 4; p++) {
                const int row = wn * 64 + p * 16 + bN;
                const int ch  = ks * 2 + bKh;
                const uint32_t rb = stgb + PAIR_B + row * 128;
                uint32_t rh[4], rl[4];
                ldsm_x4(rh, rb + ((ch       ^ (row & 7)) << 4));
                ldsm_x4(rl, rb + (((ch + 4) ^ (row & 7)) << 4));
                bh[p * 2][0] = rh[0]; bh[p * 2][1] = rh[1];
                bh[p * 2 + 1][0] = rh[2]; bh[p * 2 + 1][1] = rh[3];
                bl[p * 2][0] = rl[0]; bl[p * 2][1] = rl[1];
                bl[p * 2 + 1][0] = rl[2]; bl[p * 2 + 1][1] = rl[3];
            }
            #pragma unroll
            for (int mi = 0; mi < 4; mi++)
                #pragma unroll
                for (int nj = 0; nj < 8; nj++) {
                    mma_f16(acc[mi][nj], af[mi], bh[nj]);
                    mma_f16(acc[mi][nj], af[mi], bl[nj]);
                }
        }
        __syncthreads();   // WAR guard: next iteration overwrites the other stage
    }

    const int r0 = bm + wm * 64 + (lane >> 2);
    const int c0 = bn + wn * 64 + (lane & 3) * 2;
    #pragma unroll
    for (int mi = 0; mi < 4; mi++)
        #pragma unroll
        for (int nj = 0; nj < 8; nj++) {
            int row = r0 + mi * 16;
            int col = c0 + nj * 8;
            float2 v0 = make_float2(acc[mi][nj][0], acc[mi][nj][1]);
            float2 v1 = make_float2(acc[mi][nj][2], acc[mi][nj][3]);
            if (OUTM == 0) {
                v0.x += bias[col]; v0.y += bias[col + 1];
                v1.x += bias[col]; v1.y += bias[col + 1];
                *(float2*)(C + (size_t)row * N + col)       = v0;
                *(float2*)(C + (size_t)(row + 8) * N + col) = v1;
            } else {
                *(__half2*)(C16 + (size_t)row * N + col)       = __floats2half2_rn(v0.x, v0.y);
                *(__half2*)(C16 + (size_t)(row + 8) * N + col) = __floats2half2_rn(v1.x, v1.y);
            }
        }
}

// ---------------------------------------------------------------------------
// Flash attention, single-term fp16 mma. 3-stage KV pipeline (K,V per stage).
// qkv fp16 [4096][3072]; head h: q at h*192, k +64, v +128. Output fp16.
// ---------------------------------------------------------------------------
#define ATS    72
#define QTILE  (128 * ATS * 2)
#define KVT    (64 * ATS * 2)
#define KVSTG  (2 * KVT)
#define ASMEM  (3 * KVSTG)

__global__ __launch_bounds__(256)
void attn_mma(const __half* __restrict__ qkv, __half* __restrict__ o16)
{
    extern __shared__ char smem[];
    const uint32_t sbase = smem_u32(smem);

    const int t    = threadIdx.x;
    const int warp = t >> 5;
    const int lane = t & 31;
    const int qb   = 15 - blockIdx.x;
    const int h    = blockIdx.y;
    const int b    = blockIdx.z;
    const int wr0  = warp * 16;

    const int aRow = lane & 15;
    const int aKh  = lane >> 4;
    const int bN   = ((lane >> 4) << 3) + (lane & 7);
    const int bKh  = (lane >> 3) & 1;
    const int vRow = ((lane >> 3) & 1) * 8 + (lane & 7);
    const int vCol = (lane >> 4) * 8;

    const size_t qrow0 = (size_t)b * SEQ + qb * 128;

    #pragma unroll
    for (int it = 0; it < 4; it++) {
        const int linear = it * 256 + t;
        const int row = linear >> 3;
        const int kc  = (linear & 7) << 3;
        cp_async16(sbase + (row * ATS + kc) * 2,
                   qkv + (qrow0 + row) * 3072 + h * 192 + kc);
    }
    cp_commit();
    cp_wait<0>();
    __syncthreads();

    uint32_t qf[4][4];
    #pragma unroll
    for (int kt = 0; kt < 4; kt++)
        ldsm_x4(qf[kt], sbase + ((wr0 + aRow) * ATS + kt * 16 + aKh * 8) * 2);
    __syncthreads();

    float oacc[8][4];
    #pragma unroll
    for (int i = 0; i < 8; i++)
        #pragma unroll
        for (int j = 0; j < 4; j++) oacc[i][j] = 0.f;
    float m0 = -1e30f, m1 = -1e30f, l0 = 0.f, l1 = 0.f;

    const int r0g = qb * 128 + wr0 + (lane >> 2);
    const int r1g = r0g + 8;
    const int nblk = (qb + 1) * 2;

    auto load_kv = [&](int blk, int s) {
        const int j0 = blk * 64;
        const uint32_t kb = sbase + s * KVSTG;
        #pragma unroll
        for (int it = 0; it < 2; it++) {
            const int linear = it * 256 + t;
            const int row = linear >> 3;
            const int kc  = (linear & 7) << 3;
            uint32_t d = kb + (row * ATS + kc) * 2;
            const size_t gk = ((size_t)b * SEQ + j0 + row) * 3072 + h * 192 + 64 + kc;
            cp_async16(d,       qkv + gk);
            cp_async16(d + KVT, qkv + gk + 64);
        }
    };

    load_kv(0, 0); cp_commit();
    if (nblk > 1) { load_kv(1, 1); cp_commit(); }

    int stg = 0;
    for (int blk = 0; blk < nblk; blk++) {
        const int j0 = blk * 64;
        if (blk + 1 < nblk) cp_wait<1>(); else cp_wait<0>();
        __syncthreads();
        if (blk + 2 < nblk) {
            int ns = stg + 2; if (ns >= 3) ns -= 3;
            load_kv(blk + 2, ns); cp_commit();
        }

        const bool active = (j0 <= qb * 128 + wr0 + 15);
        if (active) {
            const uint32_t kb = sbase + stg * KVSTG;

            float sacc[8][4];
            #pragma unroll
            for (int i = 0; i < 8; i++)
                #pragma unroll
                for (int j = 0; j < 4; j++) sacc[i][j] = 0.f;
            #pragma unroll
            for (int kt = 0; kt < 4; kt++) {
                #pragma unroll
                for (int nt2 = 0; nt2 < 4; nt2++) {
                    uint32_t rk[4];
                    ldsm_x4(rk, kb + ((nt2 * 16 + bN) * ATS + kt * 16 + bKh * 8) * 2);
                    uint32_t k0[2] = {rk[0], rk[1]}, k1[2] = {rk[2], rk[3]};
                    mma_f16(sacc[nt2 * 2],     qf[kt], k0);
                    mma_f16(sacc[nt2 * 2 + 1], qf[kt], k1);
                }
            }

            if (j0 + 63 > qb * 128 + wr0) {
                #pragma unroll
                for (int nt = 0; nt < 8; nt++) {
                    const int c = j0 + nt * 8 + (lane & 3) * 2;
                    if (c     > r0g) sacc[nt][0] = -1e30f;
                    if (c + 1 > r0g) sacc[nt][1] = -1e30f;
                    if (c     > r1g) sacc[nt][2] = -1e30f;
                    if (c + 1 > r1g) sacc[nt][3] = -1e30f;
                }
            }

            float mx0 = -1e30f, mx1 = -1e30f;
            #pragma unroll
            for (int nt = 0; nt < 8; nt++) {
                mx0 = fmaxf(mx0, fmaxf(sacc[nt][0], sacc[nt][1]));
                mx1 = fmaxf(mx1, fmaxf(sacc[nt][2], sacc[nt][3]));
            }
            mx0 = fmaxf(mx0, __shfl_xor_sync(0xffffffffu, mx0, 1));
            mx0 = fmaxf(mx0, __shfl_xor_sync(0xffffffffu, mx0, 2));
            mx1 = fmaxf(mx1, __shfl_xor_sync(0xffffffffu, mx1, 1));
            mx1 = fmaxf(mx1, __shfl_xor_sync(0xffffffffu, mx1, 2));
            mx0 *= 0.125f; mx1 *= 0.125f;
            const float nm0 = fmaxf(m0, mx0), nm1 = fmaxf(m1, mx1);
            const float rs0 = __expf(m0 - nm0), rs1 = __expf(m1 - nm1);
            m0 = nm0; m1 = nm1;

            float sum0 = 0.f, sum1 = 0.f;
            #pragma unroll
            for (int nt = 0; nt < 8; nt++) {
                float p0 = __expf(fmaf(sacc[nt][0], 0.125f, -nm0));
                float p1 = __expf(fmaf(sacc[nt][1], 0.125f, -nm0));
                float p2 = __expf(fmaf(sacc[nt][2], 0.125f, -nm1));
                float p3 = __expf(fmaf(sacc[nt][3], 0.125f, -nm1));
                sacc[nt][0] = p0; sacc[nt][1] = p1;
                sacc[nt][2] = p2; sacc[nt][3] = p3;
                sum0 += p0 + p1; sum1 += p2 + p3;
            }
            sum0 += __shfl_xor_sync(0xffffffffu, sum0, 1);
            sum0 += __shfl_xor_sync(0xffffffffu, sum0, 2);
            sum1 += __shfl_xor_sync(0xffffffffu, sum1, 1);
            sum1 += __shfl_xor_sync(0xffffffffu, sum1, 2);
            l0 = l0 * rs0 + sum0;
            l1 = l1 * rs1 + sum1;

            #pragma unroll
            for (int dt = 0; dt < 8; dt++) {
                oacc[dt][0] *= rs0; oacc[dt][1] *= rs0;
                oacc[dt][2] *= rs1; oacc[dt][3] *= rs1;
            }

            #pragma unroll
            for (int kt = 0; kt < 4; kt++) {
                uint32_t vf[8][2];
                #pragma unroll
                for (int dt2 = 0; dt2 < 4; dt2++) {
                    uint32_t rv[4];
                    ldsm_x4t(rv, kb + KVT + ((kt * 16 + vRow) * ATS + dt2 * 16 + vCol) * 2);
                    vf[dt2 * 2][0] = rv[0]; vf[dt2 * 2][1] = rv[1];
                    vf[dt2 * 2 + 1][0] = rv[2]; vf[dt2 * 2 + 1][1] = rv[3];
                }
                uint32_t Pa[4];
                #pragma unroll
                for (int half_ = 0; half_ < 2; half_++) {
                    const float* s = sacc[kt * 2 + half_];
                    Pa[half_ * 2]     = pack_h2(s[0], s[1]);
                    Pa[half_ * 2 + 1] = pack_h2(s[2], s[3]);
                }
                #pragma unroll
                for (int dt = 0; dt < 8; dt++)
                    mma_f16(oacc[dt], Pa, vf[dt]);
            }
        }
        if (++stg == 3) stg = 0;
    }

    const float inv0 = 1.f / l0, inv1 = 1.f / l1;
    const size_t ro0 = (size_t)b * SEQ + qb * 128 + wr0 + (lane >> 2);
    const size_t ro1 = ro0 + 8;
    #pragma unroll
    for (int dt = 0; dt < 8; dt++) {
        const int col = h * 64 + dt * 8 + (lane & 3) * 2;
        *(__half2*)(o16 + ro0 * EMB + col) =
            __floats2half2_rn(oacc[dt][0] * inv0, oacc[dt][1] * inv0);
        *(__half2*)(o16 + ro1 * EMB + col) =
            __floats2half2_rn(oacc[dt][2] * inv1, oacc[dt][3] * inv1);
    }
}

// ---------------------------------------------------------------------------
extern "C" void kernel_launch(void* const* d_in, const int* in_sizes, int n_in,
                              void* d_out, int out_size)
{
    const float* x    = (const float*)d_in[0];
    const float* wqkv = (const float*)d_in[1];
    const float* wout = (const float*)d_in[2];
    const float* bout = (const float*)d_in[3];
    float* out = (float*)d_out;

    __half *x16, *wqh, *wql, *woh, *wol, *qkv16, *att16;
    cudaGetSymbolAddress((void**)&x16,   g_x16);
    cudaGetSymbolAddress((void**)&wqh,   g_wqh);
    cudaGetSymbolAddress((void**)&wql,   g_wql);
    cudaGetSymbolAddress((void**)&woh,   g_woh);
    cudaGetSymbolAddress((void**)&wol,   g_wol);
    cudaGetSymbolAddress((void**)&qkv16, g_qkv);
    cudaGetSymbolAddress((void**)&att16, g_att);

    cudaFuncSetAttribute(gemm_f16<2>,
                         cudaFuncAttributeMaxDynamicSharedMemorySize, GSMEM);
    cudaFuncSetAttribute(gemm_f16<0>,
                         cudaFuncAttributeMaxDynamicSharedMemorySize, GSMEM);
    cudaFuncSetAttribute(attn_mma,
                         cudaFuncAttributeMaxDynamicSharedMemorySize, ASMEM);

    // 0) conversions (one launch)
    split_all<<<SPLIT_TOT / 1024, 256>>>(x, wqkv, wout,
                                         x16, wqh, wql, woh, wol);

    // 1) QKV projection (fp16, 2-term weights) -> fp16 q,k,v
    gemm_f16<2><<<dim3(3072 / 128, ROWS / 128), 128, GSMEM>>>(
        x16, wqh, wql, nullptr, nullptr, qkv16, ROWS, 3072, EMB);

    // 2) causal flash attention (fp16) -> fp16
    attn_mma<<<dim3(SEQ / 128, NH, 2), 256, ASMEM>>>(qkv16, att16);

    // 3) out projection + bias (fp16, 2-term weights) -> fp32
    gemm_f16<0><<<dim3(EMB / 128, ROWS / 128), 128, GSMEM>>>(
        att16, woh, wol, bout, out, nullptr, ROWS, EMB, EMB);
}

// round 13
// speedup vs baseline: 2.5580x; 1.4287x over previous
#include <cuda_runtime.h>
#include <cuda_bf16.h>
#include <cuda_fp16.h>
#include <cstdint>

// ---------------------------------------------------------------------------
// bs=2, seq=2048, embed=1024, heads=16, head_dim=64
// R13: full single-term fp16 path. x, W_qkv, W_out, q/k/v, P, attn-out all
// fp16 (fp32 accumulate). Calibrated rel_err ~6.3e-4 (< 1e-3, 37% margin).
// Projection GEMM: A+B packed in one 16KB stage (A chunks 0-3, B chunks 4-7),
// 2-stage cp.async, 4 warps x 64x64, 3 CTAs/SM.
// ---------------------------------------------------------------------------

#define SEQ   2048
#define EMB   1024
#define NH    16
#define HD    64
#define ROWS  4096

__device__ __half  g_x16 [(size_t)ROWS * EMB];
__device__ __half  g_wq16[(size_t)3 * EMB * EMB];
__device__ __half  g_wo16[(size_t)EMB * EMB];
__device__ __half  g_qkv [(size_t)ROWS * 3 * EMB];
__device__ __half  g_att [(size_t)ROWS * EMB];

// ---------------------------------------------------------------------------
__device__ __forceinline__ uint32_t smem_u32(const void* p) {
    uint32_t a;
    asm("{ .reg .u64 t; cvta.to.shared.u64 t, %1; cvt.u32.u64 %0, t; }"
        : "=r"(a) : "l"(p));
    return a;
}
__device__ __forceinline__ void cp_async16(uint32_t dst, const void* src) {
    asm volatile("cp.async.cg.shared.global [%0], [%1], 16;" :: "r"(dst), "l"(src));
}
__device__ __forceinline__ void cp_commit() { asm volatile("cp.async.commit_group;"); }
template<int N>
__device__ __forceinline__ void cp_wait() {
    asm volatile("cp.async.wait_group %0;" :: "n"(N));
}
__device__ __forceinline__ void ldsm_x4(uint32_t* r, uint32_t addr) {
    asm volatile("ldmatrix.sync.aligned.m8n8.x4.shared.b16 {%0,%1,%2,%3}, [%4];"
                 : "=r"(r[0]), "=r"(r[1]), "=r"(r[2]), "=r"(r[3]) : "r"(addr));
}
__device__ __forceinline__ void ldsm_x4t(uint32_t* r, uint32_t addr) {
    asm volatile("ldmatrix.sync.aligned.m8n8.x4.trans.shared.b16 {%0,%1,%2,%3}, [%4];"
                 : "=r"(r[0]), "=r"(r[1]), "=r"(r[2]), "=r"(r[3]) : "r"(addr));
}
__device__ __forceinline__ void mma_f16(float* d, const uint32_t* a, const uint32_t* b) {
    asm volatile(
        "mma.sync.aligned.m16n8k16.row.col.f32.f16.f16.f32 "
        "{%0,%1,%2,%3}, {%4,%5,%6,%7}, {%8,%9}, {%0,%1,%2,%3};"
        : "+f"(d[0]), "+f"(d[1]), "+f"(d[2]), "+f"(d[3])
        : "r"(a[0]), "r"(a[1]), "r"(a[2]), "r"(a[3]), "r"(b[0]), "r"(b[1]));
}
__device__ __forceinline__ uint32_t pack_h2(float x, float y) {
    __half2 h = __floats2half2_rn(x, y);
    return *(uint32_t*)&h;
}

// ---------------------------------------------------------------------------
// Fused fp32 -> fp16 conversion for x, w_qkv, w_out (single launch).
// ---------------------------------------------------------------------------
#define XN   ((size_t)ROWS * EMB)
#define WQN  ((size_t)3 * EMB * EMB)
#define WON  ((size_t)EMB * EMB)
#define CVT_TOT (XN + WQN + WON)

__global__ __launch_bounds__(256)
void cvt_all(const float* __restrict__ x, const float* __restrict__ wq,
             const float* __restrict__ wo,
             __half* __restrict__ x16, __half* __restrict__ wq16,
             __half* __restrict__ wo16)
{
    size_t i = ((size_t)blockIdx.x * 256 + threadIdx.x) * 4;
    const float* in; __half* o; size_t off;
    if (i < XN)            { in = x;  o = x16;  off = i; }
    else if (i < XN + WQN) { in = wq; o = wq16; off = i - XN; }
    else                   { in = wo; o = wo16; off = i - XN - WQN; }
    float4 v = *(const float4*)(in + off);
    *(__half2*)(o + off)     = __floats2half2_rn(v.x, v.y);
    *(__half2*)(o + off + 2) = __floats2half2_rn(v.z, v.w);
}

// ---------------------------------------------------------------------------
// fp16 GEMM: C = A B^T. Output 0: fp32+bias, 2: fp16.
// CTA 128x128, 128 threads = 4 warps of 64x64, 2-stage cp.async.
// Stage = 16KB: 128 rows x 128B; A-row r in logical chunks 0-3 at slot
// (c ^ (r&7))*16, B-row r in logical chunks 4-7 at ((c+4) ^ (r&7))*16.
// ---------------------------------------------------------------------------
#define STG_B   16384
#define GSMEM   (2 * STG_B)              // 32768

template<int OUTM>
__global__ __launch_bounds__(128, 3)
void gemm_f16(const __half* __restrict__ A, const __half* __restrict__ B,
              const float* __restrict__ bias, float* __restrict__ C,
              __half* __restrict__ C16,
              int M, int N, int K)
{
    extern __shared__ char smem[];
    const uint32_t sbase = smem_u32(smem);

    const int t    = threadIdx.x;
    const int warp = t >> 5;
    const int lane = t & 31;
    const int wm   = warp >> 1;
    const int wn   = warp & 1;
    const int bm   = blockIdx.y * 128;
    const int bn   = blockIdx.x * 128;

    const int aRow = (lane & 15);
    const int aKh  = lane >> 4;
    const int bN   = ((lane >> 4) << 3) + (lane & 7);
    const int bKh  = (lane >> 3) & 1;

    float acc[4][8][4];
    #pragma unroll
    for (int i = 0; i < 4; i++)
        #pragma unroll
        for (int j = 0; j < 8; j++)
            #pragma unroll
            for (int r = 0; r < 4; r++) acc[i][j][r] = 0.f;

    const int nck = K >> 5;

    // loader: 128 threads x 8 x 16B = 16KB. lchunk 0-3: A, 4-7: B.
    const int lchunk = t & 7;
    const int lrow   = t >> 3;
    auto load_chunk = [&](int ck, int stg) {
        const int ke = (ck << 5) + (lchunk & 3) * 8;
        const __half* base = (lchunk < 4)
            ? A + (size_t)bm * K + ke
            : B + (size_t)bn * K + ke;
        #pragma unroll
        for (int it = 0; it < 8; it++) {
            const int row = it * 16 + lrow;
            uint32_t dst = sbase + stg * STG_B
                         + row * 128 + ((lchunk ^ (row & 7)) << 4);
            cp_async16(dst, base + (size_t)row * K);
        }
    };

    load_chunk(0, 0); cp_commit();

    for (int ck = 0; ck < nck; ck++) {
        if (ck + 1 < nck) {
            load_chunk(ck + 1, (ck + 1) & 1); cp_commit(); cp_wait<1>();
        } else {
            cp_wait<0>();
        }
        __syncthreads();

        const uint32_t stgb = sbase + (ck & 1) * STG_B;
        #pragma unroll
        for (int ks = 0; ks < 2; ks++) {
            uint32_t af[4][4], bf[8][2];
            #pragma unroll
            for (int mi = 0; mi < 4; mi++) {
                const int row = wm * 64 + mi * 16 + aRow;
                const int ch  = ks * 2 + aKh;
                ldsm_x4(af[mi], stgb + row * 128 + ((ch ^ (row & 7)) << 4));
            }
            #pragma unroll
            for (int p = 0; p < 4; p++) {
                const int row = wn * 64 + p * 16 + bN;
                const int ch  = ks * 2 + bKh + 4;
                uint32_t rb4[4];
                ldsm_x4(rb4, stgb + row * 128 + ((ch ^ (row & 7)) << 4));
                bf[p * 2][0] = rb4[0]; bf[p * 2][1] = rb4[1];
                bf[p * 2 + 1][0] = rb4[2]; bf[p * 2 + 1][1] = rb4[3];
            }
            #pragma unroll
            for (int mi = 0; mi < 4; mi++)
                #pragma unroll
                for (int nj = 0; nj < 8; nj++)
                    mma_f16(acc[mi][nj], af[mi], bf[nj]);
        }
        __syncthreads();   // WAR guard before overwriting the other stage
    }

    const int r0 = bm + wm * 64 + (lane >> 2);
    const int c0 = bn + wn * 64 + (lane & 3) * 2;
    #pragma unroll
    for (int mi = 0; mi < 4; mi++)
        #pragma unroll
        for (int nj = 0; nj < 8; nj++) {
            int row = r0 + mi * 16;
            int col = c0 + nj * 8;
            float2 v0 = make_float2(acc[mi][nj][0], acc[mi][nj][1]);
            float2 v1 = make_float2(acc[mi][nj][2], acc[mi][nj][3]);
            if (OUTM == 0) {
                v0.x += bias[col]; v0.y += bias[col + 1];
                v1.x += bias[col]; v1.y += bias[col + 1];
                *(float2*)(C + (size_t)row * N + col)       = v0;
                *(float2*)(C + (size_t)(row + 8) * N + col) = v1;
            } else {
                *(__half2*)(C16 + (size_t)row * N + col)       = __floats2half2_rn(v0.x, v0.y);
                *(__half2*)(C16 + (size_t)(row + 8) * N + col) = __floats2half2_rn(v1.x, v1.y);
            }
        }
}

// ---------------------------------------------------------------------------
// Flash attention, single-term fp16 mma. 3-stage KV pipeline (K,V per stage).
// qkv fp16 [4096][3072]; head h: q at h*192, k +64, v +128. Output fp16.
// (unchanged from R10/R11 — passes)
// ---------------------------------------------------------------------------
#define ATS    72
#define QTILE  (128 * ATS * 2)
#define KVT    (64 * ATS * 2)
#define KVSTG  (2 * KVT)
#define ASMEM  (3 * KVSTG)

__global__ __launch_bounds__(256)
void attn_mma(const __half* __restrict__ qkv, __half* __restrict__ o16)
{
    extern __shared__ char smem[];
    const uint32_t sbase = smem_u32(smem);

    const int t    = threadIdx.x;
    const int warp = t >> 5;
    const int lane = t & 31;
    const int qb   = 15 - blockIdx.x;
    const int h    = blockIdx.y;
    const int b    = blockIdx.z;
    const int wr0  = warp * 16;

    const int aRow = lane & 15;
    const int aKh  = lane >> 4;
    const int bN   = ((lane >> 4) << 3) + (lane & 7);
    const int bKh  = (lane >> 3) & 1;
    const int vRow = ((lane >> 3) & 1) * 8 + (lane & 7);
    const int vCol = (lane >> 4) * 8;

    const size_t qrow0 = (size_t)b * SEQ + qb * 128;

    #pragma unroll
    for (int it = 0; it < 4; it++) {
        const int linear = it * 256 + t;
        const int row = linear >> 3;
        const int kc  = (linear & 7) << 3;
        cp_async16(sbase + (row * ATS + kc) * 2,
                   qkv + (qrow0 + row) * 3072 + h * 192 + kc);
    }
    cp_commit();
    cp_wait<0>();
    __syncthreads();

    uint32_t qf[4][4];
    #pragma unroll
    for (int kt = 0; kt < 4; kt++)
        ldsm_x4(qf[kt], sbase + ((wr0 + aRow) * ATS + kt * 16 + aKh * 8) * 2);
    __syncthreads();

    float oacc[8][4];
    #pragma unroll
    for (int i = 0; i < 8; i++)
        #pragma unroll
        for (int j = 0; j < 4; j++) oacc[i][j] = 0.f;
    float m0 = -1e30f, m1 = -1e30f, l0 = 0.f, l1 = 0.f;

    const int r0g = qb * 128 + wr0 + (lane >> 2);
    const int r1g = r0g + 8;
    const int nblk = (qb + 1) * 2;

    auto load_kv = [&](int blk, int s) {
        const int j0 = blk * 64;
        const uint32_t kb = sbase + s * KVSTG;
        #pragma unroll
        for (int it = 0; it < 2; it++) {
            const int linear = it * 256 + t;
            const int row = linear >> 3;
            const int kc  = (linear & 7) << 3;
            uint32_t d = kb + (row * ATS + kc) * 2;
            const size_t gk = ((size_t)b * SEQ + j0 + row) * 3072 + h * 192 + 64 + kc;
            cp_async16(d,       qkv + gk);
            cp_async16(d + KVT, qkv + gk + 64);
        }
    };

    load_kv(0, 0); cp_commit();
    if (nblk > 1) { load_kv(1, 1); cp_commit(); }

    int stg = 0;
    for (int blk = 0; blk < nblk; blk++) {
        const int j0 = blk * 64;
        if (blk + 1 < nblk) cp_wait<1>(); else cp_wait<0>();
        __syncthreads();
        if (blk + 2 < nblk) {
            int ns = stg + 2; if (ns >= 3) ns -= 3;
            load_kv(blk + 2, ns); cp_commit();
        }

        const bool active = (j0 <= qb * 128 + wr0 + 15);
        if (active) {
            const uint32_t kb = sbase + stg * KVSTG;

            float sacc[8][4];
            #pragma unroll
            for (int i = 0; i < 8; i++)
                #pragma unroll
                for (int j = 0; j < 4; j++) sacc[i][j] = 0.f;
            #pragma unroll
            for (int kt = 0; kt < 4; kt++) {
                #pragma unroll
                for (int nt2 = 0; nt2 < 4; nt2++) {
                    uint32_t rk[4];
                    ldsm_x4(rk, kb + ((nt2 * 16 + bN) * ATS + kt * 16 + bKh * 8) * 2);
                    uint32_t k0[2] = {rk[0], rk[1]}, k1[2] = {rk[2], rk[3]};
                    mma_f16(sacc[nt2 * 2],     qf[kt], k0);
                    mma_f16(sacc[nt2 * 2 + 1], qf[kt], k1);
                }
            }

            if (j0 + 63 > qb * 128 + wr0) {
                #pragma unroll
                for (int nt = 0; nt < 8; nt++) {
                    const int c = j0 + nt * 8 + (lane & 3) * 2;
                    if (c     > r0g) sacc[nt][0] = -1e30f;
                    if (c + 1 > r0g) sacc[nt][1] = -1e30f;
                    if (c     > r1g) sacc[nt][2] = -1e30f;
                    if (c + 1 > r1g) sacc[nt][3] = -1e30f;
                }
            }

            float mx0 = -1e30f, mx1 = -1e30f;
            #pragma unroll
            for (int nt = 0; nt < 8; nt++) {
                mx0 = fmaxf(mx0, fmaxf(sacc[nt][0], sacc[nt][1]));
                mx1 = fmaxf(mx1, fmaxf(sacc[nt][2], sacc[nt][3]));
            }
            mx0 = fmaxf(mx0, __shfl_xor_sync(0xffffffffu, mx0, 1));
            mx0 = fmaxf(mx0, __shfl_xor_sync(0xffffffffu, mx0, 2));
            mx1 = fmaxf(mx1, __shfl_xor_sync(0xffffffffu, mx1, 1));
            mx1 = fmaxf(mx1, __shfl_xor_sync(0xffffffffu, mx1, 2));
            mx0 *= 0.125f; mx1 *= 0.125f;
            const float nm0 = fmaxf(m0, mx0), nm1 = fmaxf(m1, mx1);
            const float rs0 = __expf(m0 - nm0), rs1 = __expf(m1 - nm1);
            m0 = nm0; m1 = nm1;

            float sum0 = 0.f, sum1 = 0.f;
            #pragma unroll
            for (int nt = 0; nt < 8; nt++) {
                float p0 = __expf(fmaf(sacc[nt][0], 0.125f, -nm0));
                float p1 = __expf(fmaf(sacc[nt][1], 0.125f, -nm0));
                float p2 = __expf(fmaf(sacc[nt][2], 0.125f, -nm1));
                float p3 = __expf(fmaf(sacc[nt][3], 0.125f, -nm1));
                sacc[nt][0] = p0; sacc[nt][1] = p1;
                sacc[nt][2] = p2; sacc[nt][3] = p3;
                sum0 += p0 + p1; sum1 += p2 + p3;
            }
            sum0 += __shfl_xor_sync(0xffffffffu, sum0, 1);
            sum0 += __shfl_xor_sync(0xffffffffu, sum0, 2);
            sum1 += __shfl_xor_sync(0xffffffffu, sum1, 1);
            sum1 += __shfl_xor_sync(0xffffffffu, sum1, 2);
            l0 = l0 * rs0 + sum0;
            l1 = l1 * rs1 + sum1;

            #pragma unroll
            for (int dt = 0; dt < 8; dt++) {
                oacc[dt][0] *= rs0; oacc[dt][1] *= rs0;
                oacc[dt][2] *= rs1; oacc[dt][3] *= rs1;
            }

            #pragma unroll
            for (int kt = 0; kt < 4; kt++) {
                uint32_t vf[8][2];
                #pragma unroll
                for (int dt2 = 0; dt2 < 4; dt2++) {
                    uint32_t rv[4];
                    ldsm_x4t(rv, kb + KVT + ((kt * 16 + vRow) * ATS + dt2 * 16 + vCol) * 2);
                    vf[dt2 * 2][0] = rv[0]; vf[dt2 * 2][1] = rv[1];
                    vf[dt2 * 2 + 1][0] = rv[2]; vf[dt2 * 2 + 1][1] = rv[3];
                }
                uint32_t Pa[4];
                #pragma unroll
                for (int half_ = 0; half_ < 2; half_++) {
                    const float* s = sacc[kt * 2 + half_];
                    Pa[half_ * 2]     = pack_h2(s[0], s[1]);
                    Pa[half_ * 2 + 1] = pack_h2(s[2], s[3]);
                }
                #pragma unroll
                for (int dt = 0; dt < 8; dt++)
                    mma_f16(oacc[dt], Pa, vf[dt]);
            }
        }
        if (++stg == 3) stg = 0;
    }

    const float inv0 = 1.f / l0, inv1 = 1.f / l1;
    const size_t ro0 = (size_t)b * SEQ + qb * 128 + wr0 + (lane >> 2);
    const size_t ro1 = ro0 + 8;
    #pragma unroll
    for (int dt = 0; dt < 8; dt++) {
        const int col = h * 64 + dt * 8 + (lane & 3) * 2;
        *(__half2*)(o16 + ro0 * EMB + col) =
            __floats2half2_rn(oacc[dt][0] * inv0, oacc[dt][1] * inv0);
        *(__half2*)(o16 + ro1 * EMB + col) =
            __floats2half2_rn(oacc[dt][2] * inv1, oacc[dt][3] * inv1);
    }
}

// ---------------------------------------------------------------------------
extern "C" void kernel_launch(void* const* d_in, const int* in_sizes, int n_in,
                              void* d_out, int out_size)
{
    const float* x    = (const float*)d_in[0];
    const float* wqkv = (const float*)d_in[1];
    const float* wout = (const float*)d_in[2];
    const float* bout = (const float*)d_in[3];
    float* out = (float*)d_out;

    __half *x16, *wq16, *wo16, *qkv16, *att16;
    cudaGetSymbolAddress((void**)&x16,   g_x16);
    cudaGetSymbolAddress((void**)&wq16,  g_wq16);
    cudaGetSymbolAddress((void**)&wo16,  g_wo16);
    cudaGetSymbolAddress((void**)&qkv16, g_qkv);
    cudaGetSymbolAddress((void**)&att16, g_att);

    cudaFuncSetAttribute(gemm_f16<2>,
                         cudaFuncAttributeMaxDynamicSharedMemorySize, GSMEM);
    cudaFuncSetAttribute(gemm_f16<0>,
                         cudaFuncAttributeMaxDynamicSharedMemorySize, GSMEM);
    cudaFuncSetAttribute(attn_mma,
                         cudaFuncAttributeMaxDynamicSharedMemorySize, ASMEM);

    // 0) fp16 conversions (one launch)
    cvt_all<<<CVT_TOT / 1024, 256>>>(x, wqkv, wout, x16, wq16, wo16);

    // 1) QKV projection (single-term fp16) -> fp16 q,k,v
    gemm_f16<2><<<dim3(3072 / 128, ROWS / 128), 128, GSMEM>>>(
        x16, wq16, nullptr, nullptr, qkv16, ROWS, 3072, EMB);

    // 2) causal flash attention (fp16) -> fp16
    attn_mma<<<dim3(SEQ / 128, NH, 2), 256, ASMEM>>>(qkv16, att16);

    // 3) out projection + bias (single-term fp16) -> fp32
    gemm_f16<0><<<dim3(EMB / 128, ROWS / 128), 128, GSMEM>>>(
        att16, wo16, bout, out, nullptr, ROWS, EMB, EMB);
}